// round 6
// baseline (speedup 1.0000x reference)
#include <cuda_runtime.h>
#include <cuda_fp16.h>
#include <math.h>
#include <stdint.h>

#define BB 4
#define CC 64
#define HH 96
#define WW 96
#define NN (HH*WW)      // 9216
#define HP (HH/2)
#define WP (WW/2)
#define MM (HP*WP)      // 2304
#define KK 64

// Scratch (no allocations allowed)
__device__ float g_q  [BB*KK*NN];   // q, [b][k][n]
__device__ float g_k  [BB*KK*MM];   // k, [b][k][m]
__device__ float g_v  [BB*CC*MM];   // pooled x, [b][c][m]
__device__ float g_c2p[BB*CC*MM];   // pooled c2, [b][c][m]
__device__ float g_ea [BB*MM];      // sigmoid edge gate, [b][m]

// ---- mma helpers ----------------------------------------------------------
__device__ __forceinline__ void ldm4(uint32_t* r, uint32_t addr) {
    asm volatile("ldmatrix.sync.aligned.m8n8.x4.shared.b16 {%0,%1,%2,%3}, [%4];"
        : "=r"(r[0]), "=r"(r[1]), "=r"(r[2]), "=r"(r[3]) : "r"(addr));
}
__device__ __forceinline__ void mma16(float* d, const uint32_t* a, uint32_t b0, uint32_t b1) {
    asm volatile("mma.sync.aligned.m16n8k16.row.col.f32.f16.f16.f32 "
        "{%0,%1,%2,%3}, {%4,%5,%6,%7}, {%8,%9}, {%0,%1,%2,%3};"
        : "+f"(d[0]), "+f"(d[1]), "+f"(d[2]), "+f"(d[3])
        : "r"(a[0]), "r"(a[1]), "r"(a[2]), "r"(a[3]), "r"(b0), "r"(b1));
}
__device__ __forceinline__ uint32_t smem_u32(const void* p) {
    return (uint32_t)__cvta_generic_to_shared(p);
}
// pack (lo,hi) floats -> f16x2 (elem0 = lo)
__device__ __forceinline__ uint32_t pack_h2(float lo, float hi) {
    uint32_t r; asm("cvt.rn.f16x2.f32 %0, %1, %2;" : "=r"(r) : "f"(hi), "f"(lo)); return r;
}

// smem regions (BYTE offsets), 128B rows, 16B-unit XOR(row&7) swizzle
#define B_QHI 0        // [128 r][64 d] f16
#define B_QLO 16384
#define B_KHI 32768    // [64 key][64 d] f16
#define B_KLO 40960
#define B_VS  49152    // [64 ch][64 key] f16
#define B_PS  57344    // [128 r][64 key] f16 (per-warp private rows)
#define B_EA  73728    // [64] float
#define ATTN_SMEM_BYTES 73984

// ---------------------------------------------------------------------------
// P0: 2x2 maxpool of x and c2 -> g_v, g_c2p. Pure streaming.
// ---------------------------------------------------------------------------
__global__ void __launch_bounds__(256) pool_kernel(
    const float* __restrict__ x, const float* __restrict__ c2)
{
    int idx = blockIdx.x * 256 + threadIdx.x;
    if (idx >= BB*CC*MM) return;
    int m = idx % MM;
    int bc = idx / MM;            // b*CC + c
    int py = m / WP, px = m % WP;
    int base = (bc*HH + 2*py)*WW + 2*px;
    float2 a0 = *(const float2*)(x + base);
    float2 a1 = *(const float2*)(x + base + WW);
    g_v[idx] = fmaxf(fmaxf(a0.x, a0.y), fmaxf(a1.x, a1.y));
    float2 b0 = *(const float2*)(c2 + base);
    float2 b1 = *(const float2*)(c2 + base + WW);
    g_c2p[idx] = fmaxf(fmaxf(b0.x, b0.y), fmaxf(b1.x, b1.y));
}

// ---------------------------------------------------------------------------
// P1: on pooled data: k = Wq*xp + bq, edge gate ea. Block = 64 pooled pixels.
// ---------------------------------------------------------------------------
__global__ void __launch_bounds__(256) kvea_kernel(
    const float* __restrict__ w_ea1, const float* __restrict__ bn_w,
    const float* __restrict__ bn_b,  const float* __restrict__ bn_m,
    const float* __restrict__ bn_v,  const float* __restrict__ w_ea2,
    const float* __restrict__ b_ea2, const float* __restrict__ w_q,
    const float* __restrict__ b_q)
{
    extern __shared__ float sm[];
    float* sWq  = sm;                 // [64][65]
    float* sW1  = sWq  + 64*65;       // [64][129]
    float* sXp  = sW1  + 64*129;      // [64][65]
    float* sC2p = sXp  + 64*65;       // [64][65]
    float* sH   = sC2p + 64*65;       // [64][65]

    const int b   = blockIdx.y;
    const int m0  = blockIdx.x * 64;
    const int tid = threadIdx.x;

    for (int i = tid; i < 64*64;  i += 256) sWq[(i>>6)*65  + (i&63)]  = w_q[i];
    for (int i = tid; i < 64*128; i += 256) sW1[(i>>7)*129 + (i&127)] = w_ea1[i];
    for (int i = tid; i < 4096; i += 256) {
        int c = i >> 6, p = i & 63;
        sXp [p*65 + c] = g_v  [(b*CC + c)*MM + m0 + p];
        sC2p[p*65 + c] = g_c2p[(b*CC + c)*MM + m0 + p];
    }
    __syncthreads();

    for (int job = tid; job < 1024; job += 256) {
        int og = (job >> 6) << 2;
        int p  = job & 63;
        const float* xr = sXp  + p*65;
        const float* cr = sC2p + p*65;
        const float *w0 = sWq + og*65, *w1 = w0+65, *w2 = w0+130, *w3 = w0+195;
        float a0 = b_q[og], a1 = b_q[og+1], a2 = b_q[og+2], a3 = b_q[og+3];
        #pragma unroll 8
        for (int c = 0; c < 64; c++) {
            float xv = xr[c];
            a0 += w0[c]*xv; a1 += w1[c]*xv; a2 += w2[c]*xv; a3 += w3[c]*xv;
        }
        g_k[(b*KK+og  )*MM + m0 + p] = a0;
        g_k[(b*KK+og+1)*MM + m0 + p] = a1;
        g_k[(b*KK+og+2)*MM + m0 + p] = a2;
        g_k[(b*KK+og+3)*MM + m0 + p] = a3;

        const float *u0 = sW1 + og*129, *u1 = u0+129, *u2 = u0+258, *u3 = u0+387;
        float h0=0.f, h1=0.f, h2=0.f, h3=0.f;
        #pragma unroll 8
        for (int c = 0; c < 64; c++) {
            float cv = cr[c];
            h0 += u0[c]*cv; h1 += u1[c]*cv; h2 += u2[c]*cv; h3 += u3[c]*cv;
        }
        #pragma unroll 8
        for (int c = 0; c < 64; c++) {
            float xv = xr[c];
            h0 += u0[64+c]*xv; h1 += u1[64+c]*xv; h2 += u2[64+c]*xv; h3 += u3[64+c]*xv;
        }
        float hh[4] = {h0, h1, h2, h3};
        #pragma unroll
        for (int k2 = 0; k2 < 4; k2++) {
            int o = og + k2;
            float scale = bn_w[o] * rsqrtf(bn_v[o] + 1e-5f);
            float hv = (hh[k2] - bn_m[o]) * scale + bn_b[o];
            sH[p*65 + o] = fmaxf(hv, 0.f);
        }
    }
    __syncthreads();

    if (tid < 64) {
        int p = tid;
        const float* hr = sH + p*65;
        float acc = b_ea2[0];
        #pragma unroll 16
        for (int o = 0; o < 64; o++) acc += w_ea2[o]*hr[o];
        g_ea[b*MM + m0 + p] = 1.f / (1.f + __expf(-acc));
    }
}

// ---------------------------------------------------------------------------
// P2: q = Wq * x + bq at full resolution (4-way ILP)
// ---------------------------------------------------------------------------
__global__ void __launch_bounds__(256) q_kernel(
    const float* __restrict__ x, const float* __restrict__ w_q,
    const float* __restrict__ b_q)
{
    __shared__ float sX [64*65];
    __shared__ float sWq[64*65];
    const int b   = blockIdx.y;
    const int n0  = blockIdx.x * 64;
    const int tid = threadIdx.x;

    for (int i = tid; i < 64*64; i += 256) sWq[(i>>6)*65 + (i&63)] = w_q[i];
    for (int i = tid; i < 64*64; i += 256) {
        int c = i >> 6, p = i & 63;
        sX[p*65 + c] = x[(b*CC + c)*NN + n0 + p];
    }
    __syncthreads();
    for (int job = tid; job < 1024; job += 256) {
        int og = (job >> 6) << 2;
        int p  = job & 63;
        const float* xr = sX + p*65;
        const float *w0 = sWq + og*65, *w1 = w0+65, *w2 = w0+130, *w3 = w0+195;
        float a0 = b_q[og], a1 = b_q[og+1], a2 = b_q[og+2], a3 = b_q[og+3];
        #pragma unroll 8
        for (int c = 0; c < 64; c++) {
            float xv = xr[c];
            a0 += w0[c]*xv; a1 += w1[c]*xv; a2 += w2[c]*xv; a3 += w3[c]*xv;
        }
        g_q[(b*KK+og  )*NN + n0 + p] = a0;
        g_q[(b*KK+og+1)*NN + n0 + p] = a1;
        g_q[(b*KK+og+2)*NN + n0 + p] = a2;
        g_q[(b*KK+og+3)*NN + n0 + p] = a3;
    }
}

// ---------------------------------------------------------------------------
// A: flash attention, fp16 m16n8k16 mma.
// QK: 3-term fp16 split (hi*hi + hi*lo + lo*hi). PV: single fp16 x fp16.
// Block = 128 query rows, 8 warps x 16 rows, key tiles of 64.
// ---------------------------------------------------------------------------
__global__ void __launch_bounds__(256) attn_kernel(
    const float* __restrict__ x, const float* __restrict__ gamma,
    float* __restrict__ out)
{
    extern __shared__ float sm[];
    const uint32_t sb = smem_u32(sm);
    char* smc = (char*)sm;

    const int b    = blockIdx.y;
    const int n0   = blockIdx.x * 128;
    const int tid  = threadIdx.x;
    const int lane = tid & 31;
    const int warp = tid >> 5;
    const int rbase = warp * 16;

    const int lrow  = lane & 15;        // ldmatrix row-in-16
    const int khalf = lane >> 4;        // ldmatrix k-half unit
    const int gid   = lane >> 2;
    const int colb  = 2 * (lane & 3);
    const int prow0 = rbase + gid;
    const int arow  = rbase + lrow;     // A-frag row (Q / P)

    const float g = gamma[0];

    // ---- load Q block, split to fp16 hi/lo --------------------------------
    for (int i = tid; i < 8192; i += 256) {
        int d = i >> 7, r = i & 127;
        float q = g_q[(b*KK + d)*NN + n0 + r];
        __half hi = __float2half_rn(q);
        __half lo = __float2half_rn(q - __half2float(hi));
        int off = r*128 + ((((d>>3) ^ (r&7)))<<4) + (d&7)*2;
        *(__half*)(smc + B_QHI + off) = hi;
        *(__half*)(smc + B_QLO + off) = lo;
    }

    float m0 = -1e30f, m1 = -1e30f, l0 = 0.f, l1 = 0.f;
    float O[8][4];
    #pragma unroll
    for (int nc = 0; nc < 8; nc++)
        #pragma unroll
        for (int j = 0; j < 4; j++) O[nc][j] = 0.f;

    for (int t = 0; t < MM/64; t++) {
        const int mb = t * 64;
        __syncthreads();   // previous tile's K/V reads done
        for (int i = tid; i < 4096; i += 256) {
            int d = i >> 6, j = i & 63;
            float k = g_k[(b*KK + d)*MM + mb + j];
            __half hi = __float2half_rn(k);
            __half lo = __float2half_rn(k - __half2float(hi));
            int koff = j*128 + ((((d>>3) ^ (j&7)))<<4) + (d&7)*2;
            *(__half*)(smc + B_KHI + koff) = hi;
            *(__half*)(smc + B_KLO + koff) = lo;
            float v = g_v[(b*CC + d)*MM + mb + j];   // d = channel here
            int voff = d*128 + ((((j>>3) ^ (d&7)))<<4) + (j&7)*2;
            *(__half*)(smc + B_VS + voff) = __float2half_rn(v);
        }
        if (tid < 64) *(float*)(smc + B_EA + tid*4) = g_ea[b*MM + mb + tid];
        __syncthreads();

        // ---- S = Q K^T (3-term fp16 split) --------------------------------
        float S[8][4];
        #pragma unroll
        for (int nc = 0; nc < 8; nc++)
            #pragma unroll
            for (int j = 0; j < 4; j++) S[nc][j] = 0.f;

        #pragma unroll
        for (int kc = 0; kc < 4; kc++) {
            const int unit = kc*2 + khalf;
            uint32_t ah[4], al[4];
            uint32_t aoff = arow*128 + (((unit ^ (arow&7)))<<4);
            ldm4(ah, sb + B_QHI + aoff);
            ldm4(al, sb + B_QLO + aoff);
            #pragma unroll
            for (int nc2 = 0; nc2 < 4; nc2++) {
                int key = nc2*16 + lrow;
                uint32_t boff = key*128 + (((unit ^ (key&7)))<<4);
                uint32_t bh[4], bl[4];
                ldm4(bh, sb + B_KHI + boff);
                ldm4(bl, sb + B_KLO + boff);
                mma16(S[nc2*2],   ah, bh[0], bh[2]);
                mma16(S[nc2*2+1], ah, bh[1], bh[3]);
                mma16(S[nc2*2],   ah, bl[0], bl[2]);
                mma16(S[nc2*2+1], ah, bl[1], bl[3]);
                mma16(S[nc2*2],   al, bh[0], bh[2]);
                mma16(S[nc2*2+1], al, bh[1], bh[3]);
            }
        }

        // ---- edge gate ----------------------------------------------------
        #pragma unroll
        for (int nc = 0; nc < 8; nc++) {
            float2 e = *(float2*)(smc + B_EA + (nc*8 + colb)*4);
            S[nc][0] *= e.x; S[nc][1] *= e.y;
            S[nc][2] *= e.x; S[nc][3] *= e.y;
        }

        // ---- online softmax ----------------------------------------------
        float rm0 = -1e30f, rm1 = -1e30f;
        #pragma unroll
        for (int nc = 0; nc < 8; nc++) {
            rm0 = fmaxf(rm0, fmaxf(S[nc][0], S[nc][1]));
            rm1 = fmaxf(rm1, fmaxf(S[nc][2], S[nc][3]));
        }
        rm0 = fmaxf(rm0, __shfl_xor_sync(0xffffffffu, rm0, 1));
        rm0 = fmaxf(rm0, __shfl_xor_sync(0xffffffffu, rm0, 2));
        rm1 = fmaxf(rm1, __shfl_xor_sync(0xffffffffu, rm1, 1));
        rm1 = fmaxf(rm1, __shfl_xor_sync(0xffffffffu, rm1, 2));
        float mn0 = fmaxf(m0, rm0), mn1 = fmaxf(m1, rm1);
        float a0 = __expf(m0 - mn0), a1 = __expf(m1 - mn1);
        m0 = mn0; m1 = mn1;
        float s0 = 0.f, s1 = 0.f;
        #pragma unroll
        for (int nc = 0; nc < 8; nc++) {
            S[nc][0] = __expf(S[nc][0] - mn0); s0 += S[nc][0];
            S[nc][1] = __expf(S[nc][1] - mn0); s0 += S[nc][1];
            S[nc][2] = __expf(S[nc][2] - mn1); s1 += S[nc][2];
            S[nc][3] = __expf(S[nc][3] - mn1); s1 += S[nc][3];
        }
        s0 += __shfl_xor_sync(0xffffffffu, s0, 1);
        s0 += __shfl_xor_sync(0xffffffffu, s0, 2);
        s1 += __shfl_xor_sync(0xffffffffu, s1, 1);
        s1 += __shfl_xor_sync(0xffffffffu, s1, 2);
        l0 = l0*a0 + s0;
        l1 = l1*a1 + s1;
        #pragma unroll
        for (int nc = 0; nc < 8; nc++) {
            O[nc][0] *= a0; O[nc][1] *= a0;
            O[nc][2] *= a1; O[nc][3] *= a1;
        }

        // ---- P -> smem fp16 (per-warp-private rows: warp sync only) -------
        #pragma unroll
        for (int nc = 0; nc < 8; nc++) {
            uint32_t p2a = pack_h2(S[nc][0], S[nc][1]);
            int off0 = prow0*128 + (((nc ^ (prow0&7)))<<4) + (lane&3)*4;
            *(uint32_t*)(smc + B_PS + off0) = p2a;
            uint32_t p2b = pack_h2(S[nc][2], S[nc][3]);
            int off1 = (prow0+8)*128 + (((nc ^ ((prow0+8)&7)))<<4) + (lane&3)*4;
            *(uint32_t*)(smc + B_PS + off1) = p2b;
        }
        __syncwarp();

        // ---- O += P V^T (single-term fp16) --------------------------------
        #pragma unroll
        for (int kc = 0; kc < 4; kc++) {
            const int unit = kc*2 + khalf;
            uint32_t ps[4];
            uint32_t aoff = arow*128 + (((unit ^ (arow&7)))<<4);
            ldm4(ps, sb + B_PS + aoff);
            #pragma unroll
            for (int nc2 = 0; nc2 < 4; nc2++) {
                int ch = nc2*16 + lrow;
                uint32_t boff = ch*128 + (((unit ^ (ch&7)))<<4);
                uint32_t bv[4];
                ldm4(bv, sb + B_VS + boff);
                mma16(O[nc2*2],   ps, bv[0], bv[2]);
                mma16(O[nc2*2+1], ps, bv[1], bv[3]);
            }
        }
    }

    // ---- finalize ---------------------------------------------------------
    float inv0 = 1.f / l0, inv1 = 1.f / l1;
    #pragma unroll
    for (int nc = 0; nc < 8; nc++) {
        O[nc][0] *= inv0; O[nc][1] *= inv0;
        O[nc][2] *= inv1; O[nc][3] *= inv1;
    }

    __syncthreads();   // everyone done with Q region
    float* Ost = sm;   // [64 ch][128 row] fp32, aliases Q region (32 KB)
    #pragma unroll
    for (int nc = 0; nc < 8; nc++) {
        int c0 = nc*8 + colb;
        Ost[(c0    )*128 + prow0    ] = O[nc][0];
        Ost[(c0 + 1)*128 + prow0    ] = O[nc][1];
        Ost[(c0    )*128 + prow0 + 8] = O[nc][2];
        Ost[(c0 + 1)*128 + prow0 + 8] = O[nc][3];
    }
    __syncthreads();
    for (int i = tid; i < 8192; i += 256) {
        int c = i >> 7, r = i & 127;
        int gi = (b*CC + c)*NN + n0 + r;
        out[gi] = g * Ost[c*128 + r] + x[gi];
    }
}

// ---------------------------------------------------------------------------
extern "C" void kernel_launch(void* const* d_in, const int* in_sizes, int n_in,
                              void* d_out, int out_size)
{
    const float* c2    = (const float*)d_in[0];
    const float* x     = (const float*)d_in[1];
    const float* w_ea1 = (const float*)d_in[2];
    const float* bn_w  = (const float*)d_in[3];
    const float* bn_b  = (const float*)d_in[4];
    const float* bn_m  = (const float*)d_in[5];
    const float* bn_v  = (const float*)d_in[6];
    const float* w_ea2 = (const float*)d_in[7];
    const float* b_ea2 = (const float*)d_in[8];
    const float* w_q   = (const float*)d_in[9];
    const float* b_q   = (const float*)d_in[10];
    const float* gamma = (const float*)d_in[11];
    float* out = (float*)d_out;

    const int KVEA_SMEM = 64*(65*4 + 129) * (int)sizeof(float);   // 99584 B

    cudaFuncSetAttribute(kvea_kernel, cudaFuncAttributeMaxDynamicSharedMemorySize, KVEA_SMEM);
    cudaFuncSetAttribute(attn_kernel, cudaFuncAttributeMaxDynamicSharedMemorySize, ATTN_SMEM_BYTES);

    pool_kernel<<<(BB*CC*MM + 255)/256, 256>>>(x, c2);
    kvea_kernel<<<dim3(MM/64, BB), 256, KVEA_SMEM>>>(w_ea1, bn_w, bn_b, bn_m,
                                                     bn_v, w_ea2, b_ea2, w_q, b_q);
    q_kernel<<<dim3(NN/64, BB), 256>>>(x, w_q, b_q);
    attn_kernel<<<dim3(NN/128, BB), 256, ATTN_SMEM_BYTES>>>(x, gamma, out);
}

// round 7
// speedup vs baseline: 1.2862x; 1.2862x over previous
#include <cuda_runtime.h>
#include <cuda_fp16.h>
#include <math.h>
#include <stdint.h>

#define BB 4
#define CC 64
#define HH 96
#define WW 96
#define NN (HH*WW)      // 9216
#define HP (HH/2)
#define WP (WW/2)
#define MM (HP*WP)      // 2304
#define KK 64

// Scratch (no allocations allowed)
__device__ float g_q  [BB*KK*NN];   // q, [b][k][n]
__device__ float g_k  [BB*KK*MM];   // k, [b][k][m]
__device__ float g_v  [BB*CC*MM];   // pooled x, [b][c][m]
__device__ float g_c2p[BB*CC*MM];   // pooled c2, [b][c][m]
__device__ float g_ea [BB*MM];      // sigmoid edge gate, [b][m]

// ---- mma helpers ----------------------------------------------------------
__device__ __forceinline__ void ldm4(uint32_t* r, uint32_t addr) {
    asm volatile("ldmatrix.sync.aligned.m8n8.x4.shared.b16 {%0,%1,%2,%3}, [%4];"
        : "=r"(r[0]), "=r"(r[1]), "=r"(r[2]), "=r"(r[3]) : "r"(addr));
}
__device__ __forceinline__ void mma16(float* d, const uint32_t* a, uint32_t b0, uint32_t b1) {
    asm volatile("mma.sync.aligned.m16n8k16.row.col.f32.f16.f16.f32 "
        "{%0,%1,%2,%3}, {%4,%5,%6,%7}, {%8,%9}, {%0,%1,%2,%3};"
        : "+f"(d[0]), "+f"(d[1]), "+f"(d[2]), "+f"(d[3])
        : "r"(a[0]), "r"(a[1]), "r"(a[2]), "r"(a[3]), "r"(b0), "r"(b1));
}
__device__ __forceinline__ uint32_t smem_u32(const void* p) {
    return (uint32_t)__cvta_generic_to_shared(p);
}
// pack (lo,hi) floats -> f16x2 (elem0 = lo)
__device__ __forceinline__ uint32_t pack_h2(float lo, float hi) {
    uint32_t r; asm("cvt.rn.f16x2.f32 %0, %1, %2;" : "=r"(r) : "f"(hi), "f"(lo)); return r;
}

// smem regions (BYTE offsets), 128B rows, 16B-unit XOR(row&7) swizzle
#define B_QHI 0        // [128 r][64 d] f16
#define B_QLO 16384
#define B_KHI 32768    // [64 key][64 d] f16
#define B_KLO 40960
#define B_VS  49152    // [64 ch][64 key] f16
#define B_PS  57344    // [128 r][64 key] f16 (per-warp private rows)
#define B_EA  73728    // [64] float
#define ATTN_SMEM_BYTES 73984

// ---------------------------------------------------------------------------
// P0: 2x2 maxpool of x and c2 -> g_v, g_c2p. Pure streaming.
// ---------------------------------------------------------------------------
__global__ void __launch_bounds__(256) pool_kernel(
    const float* __restrict__ x, const float* __restrict__ c2)
{
    int idx = blockIdx.x * 256 + threadIdx.x;
    if (idx >= BB*CC*MM) return;
    int m = idx % MM;
    int bc = idx / MM;            // b*CC + c
    int py = m / WP, px = m % WP;
    int base = (bc*HH + 2*py)*WW + 2*px;
    float2 a0 = *(const float2*)(x + base);
    float2 a1 = *(const float2*)(x + base + WW);
    g_v[idx] = fmaxf(fmaxf(a0.x, a0.y), fmaxf(a1.x, a1.y));
    float2 b0 = *(const float2*)(c2 + base);
    float2 b1 = *(const float2*)(c2 + base + WW);
    g_c2p[idx] = fmaxf(fmaxf(b0.x, b0.y), fmaxf(b1.x, b1.y));
}

// ---------------------------------------------------------------------------
// P1: on pooled data: k = Wq*xp + bq, edge gate ea. Block = 64 pooled pixels.
// ---------------------------------------------------------------------------
__global__ void __launch_bounds__(256) kvea_kernel(
    const float* __restrict__ w_ea1, const float* __restrict__ bn_w,
    const float* __restrict__ bn_b,  const float* __restrict__ bn_m,
    const float* __restrict__ bn_v,  const float* __restrict__ w_ea2,
    const float* __restrict__ b_ea2, const float* __restrict__ w_q,
    const float* __restrict__ b_q)
{
    extern __shared__ float sm[];
    float* sWq  = sm;                 // [64][65]
    float* sW1  = sWq  + 64*65;       // [64][129]
    float* sXp  = sW1  + 64*129;      // [64][65]
    float* sC2p = sXp  + 64*65;       // [64][65]
    float* sH   = sC2p + 64*65;       // [64][65]

    const int b   = blockIdx.y;
    const int m0  = blockIdx.x * 64;
    const int tid = threadIdx.x;

    for (int i = tid; i < 64*64;  i += 256) sWq[(i>>6)*65  + (i&63)]  = w_q[i];
    for (int i = tid; i < 64*128; i += 256) sW1[(i>>7)*129 + (i&127)] = w_ea1[i];
    for (int i = tid; i < 4096; i += 256) {
        int c = i >> 6, p = i & 63;
        sXp [p*65 + c] = g_v  [(b*CC + c)*MM + m0 + p];
        sC2p[p*65 + c] = g_c2p[(b*CC + c)*MM + m0 + p];
    }
    __syncthreads();

    for (int job = tid; job < 1024; job += 256) {
        int og = (job >> 6) << 2;
        int p  = job & 63;
        const float* xr = sXp  + p*65;
        const float* cr = sC2p + p*65;
        const float *w0 = sWq + og*65, *w1 = w0+65, *w2 = w0+130, *w3 = w0+195;
        float a0 = b_q[og], a1 = b_q[og+1], a2 = b_q[og+2], a3 = b_q[og+3];
        #pragma unroll 8
        for (int c = 0; c < 64; c++) {
            float xv = xr[c];
            a0 += w0[c]*xv; a1 += w1[c]*xv; a2 += w2[c]*xv; a3 += w3[c]*xv;
        }
        g_k[(b*KK+og  )*MM + m0 + p] = a0;
        g_k[(b*KK+og+1)*MM + m0 + p] = a1;
        g_k[(b*KK+og+2)*MM + m0 + p] = a2;
        g_k[(b*KK+og+3)*MM + m0 + p] = a3;

        const float *u0 = sW1 + og*129, *u1 = u0+129, *u2 = u0+258, *u3 = u0+387;
        float h0=0.f, h1=0.f, h2=0.f, h3=0.f;
        #pragma unroll 8
        for (int c = 0; c < 64; c++) {
            float cv = cr[c];
            h0 += u0[c]*cv; h1 += u1[c]*cv; h2 += u2[c]*cv; h3 += u3[c]*cv;
        }
        #pragma unroll 8
        for (int c = 0; c < 64; c++) {
            float xv = xr[c];
            h0 += u0[64+c]*xv; h1 += u1[64+c]*xv; h2 += u2[64+c]*xv; h3 += u3[64+c]*xv;
        }
        float hh[4] = {h0, h1, h2, h3};
        #pragma unroll
        for (int k2 = 0; k2 < 4; k2++) {
            int o = og + k2;
            float scale = bn_w[o] * rsqrtf(bn_v[o] + 1e-5f);
            float hv = (hh[k2] - bn_m[o]) * scale + bn_b[o];
            sH[p*65 + o] = fmaxf(hv, 0.f);
        }
    }
    __syncthreads();

    if (tid < 64) {
        int p = tid;
        const float* hr = sH + p*65;
        float acc = b_ea2[0];
        #pragma unroll 16
        for (int o = 0; o < 64; o++) acc += w_ea2[o]*hr[o];
        g_ea[b*MM + m0 + p] = 1.f / (1.f + __expf(-acc));
    }
}

// ---------------------------------------------------------------------------
// P2: q = Wq * x + bq at full resolution (4-way ILP)
// ---------------------------------------------------------------------------
__global__ void __launch_bounds__(256) q_kernel(
    const float* __restrict__ x, const float* __restrict__ w_q,
    const float* __restrict__ b_q)
{
    __shared__ float sX [64*65];
    __shared__ float sWq[64*65];
    const int b   = blockIdx.y;
    const int n0  = blockIdx.x * 64;
    const int tid = threadIdx.x;

    for (int i = tid; i < 64*64; i += 256) sWq[(i>>6)*65 + (i&63)] = w_q[i];
    for (int i = tid; i < 64*64; i += 256) {
        int c = i >> 6, p = i & 63;
        sX[p*65 + c] = x[(b*CC + c)*NN + n0 + p];
    }
    __syncthreads();
    for (int job = tid; job < 1024; job += 256) {
        int og = (job >> 6) << 2;
        int p  = job & 63;
        const float* xr = sX + p*65;
        const float *w0 = sWq + og*65, *w1 = w0+65, *w2 = w0+130, *w3 = w0+195;
        float a0 = b_q[og], a1 = b_q[og+1], a2 = b_q[og+2], a3 = b_q[og+3];
        #pragma unroll 8
        for (int c = 0; c < 64; c++) {
            float xv = xr[c];
            a0 += w0[c]*xv; a1 += w1[c]*xv; a2 += w2[c]*xv; a3 += w3[c]*xv;
        }
        g_q[(b*KK+og  )*NN + n0 + p] = a0;
        g_q[(b*KK+og+1)*NN + n0 + p] = a1;
        g_q[(b*KK+og+2)*NN + n0 + p] = a2;
        g_q[(b*KK+og+3)*NN + n0 + p] = a3;
    }
}

// ---------------------------------------------------------------------------
// A: flash attention, fp16 m16n8k16 mma, 2 blocks/SM (reg-capped).
// QK: 3-term fp16 split. PV: single fp16 x fp16.
// Block = 128 query rows, 8 warps x 16 rows, key tiles of 64.
// ---------------------------------------------------------------------------
__global__ void __launch_bounds__(256, 2) attn_kernel(
    const float* __restrict__ x, const float* __restrict__ gamma,
    float* __restrict__ out)
{
    extern __shared__ float sm[];
    const uint32_t sb = smem_u32(sm);
    char* smc = (char*)sm;

    const int b    = blockIdx.y;
    const int n0   = blockIdx.x * 128;
    const int tid  = threadIdx.x;
    const int lane = tid & 31;
    const int warp = tid >> 5;
    const int rbase = warp * 16;

    const int lrow  = lane & 15;        // ldmatrix row-in-16
    const int khalf = lane >> 4;        // ldmatrix k-half unit
    const int gid   = lane >> 2;
    const int colb  = 2 * (lane & 3);
    const int prow0 = rbase + gid;
    const int arow  = rbase + lrow;     // A-frag row (Q / P)

    const float g = gamma[0];

    // ---- load Q block, split to fp16 hi/lo --------------------------------
    for (int i = tid; i < 8192; i += 256) {
        int d = i >> 7, r = i & 127;
        float q = g_q[(b*KK + d)*NN + n0 + r];
        __half hi = __float2half_rn(q);
        __half lo = __float2half_rn(q - __half2float(hi));
        int off = r*128 + ((((d>>3) ^ (r&7)))<<4) + (d&7)*2;
        *(__half*)(smc + B_QHI + off) = hi;
        *(__half*)(smc + B_QLO + off) = lo;
    }

    float m0 = -1e30f, m1 = -1e30f, l0 = 0.f, l1 = 0.f;
    float O[8][4];
    #pragma unroll
    for (int nc = 0; nc < 8; nc++)
        #pragma unroll
        for (int j = 0; j < 4; j++) O[nc][j] = 0.f;

    for (int t = 0; t < MM/64; t++) {
        const int mb = t * 64;
        __syncthreads();   // previous tile's K/V reads done
        for (int i = tid; i < 4096; i += 256) {
            int d = i >> 6, j = i & 63;
            float k = g_k[(b*KK + d)*MM + mb + j];
            __half hi = __float2half_rn(k);
            __half lo = __float2half_rn(k - __half2float(hi));
            int koff = j*128 + ((((d>>3) ^ (j&7)))<<4) + (d&7)*2;
            *(__half*)(smc + B_KHI + koff) = hi;
            *(__half*)(smc + B_KLO + koff) = lo;
            float v = g_v[(b*CC + d)*MM + mb + j];   // d = channel here
            int voff = d*128 + ((((j>>3) ^ (d&7)))<<4) + (j&7)*2;
            *(__half*)(smc + B_VS + voff) = __float2half_rn(v);
        }
        if (tid < 64) *(float*)(smc + B_EA + tid*4) = g_ea[b*MM + mb + tid];
        __syncthreads();

        // ---- S = Q K^T (3-term fp16 split) --------------------------------
        float S[8][4];
        #pragma unroll
        for (int nc = 0; nc < 8; nc++)
            #pragma unroll
            for (int j = 0; j < 4; j++) S[nc][j] = 0.f;

        #pragma unroll
        for (int kc = 0; kc < 4; kc++) {
            const int unit = kc*2 + khalf;
            uint32_t ah[4], al[4];
            uint32_t aoff = arow*128 + (((unit ^ (arow&7)))<<4);
            ldm4(ah, sb + B_QHI + aoff);
            ldm4(al, sb + B_QLO + aoff);
            #pragma unroll
            for (int nc2 = 0; nc2 < 4; nc2++) {
                int key = nc2*16 + lrow;
                uint32_t boff = key*128 + (((unit ^ (key&7)))<<4);
                // load bh, use it fully, then bl (shrinks live fragment set)
                uint32_t bh[4];
                ldm4(bh, sb + B_KHI + boff);
                mma16(S[nc2*2],   ah, bh[0], bh[2]);
                mma16(S[nc2*2+1], ah, bh[1], bh[3]);
                mma16(S[nc2*2],   al, bh[0], bh[2]);
                mma16(S[nc2*2+1], al, bh[1], bh[3]);
                uint32_t bl[4];
                ldm4(bl, sb + B_KLO + boff);
                mma16(S[nc2*2],   ah, bl[0], bl[2]);
                mma16(S[nc2*2+1], ah, bl[1], bl[3]);
            }
        }

        // ---- edge gate ----------------------------------------------------
        #pragma unroll
        for (int nc = 0; nc < 8; nc++) {
            float2 e = *(float2*)(smc + B_EA + (nc*8 + colb)*4);
            S[nc][0] *= e.x; S[nc][1] *= e.y;
            S[nc][2] *= e.x; S[nc][3] *= e.y;
        }

        // ---- online softmax ----------------------------------------------
        float rm0 = -1e30f, rm1 = -1e30f;
        #pragma unroll
        for (int nc = 0; nc < 8; nc++) {
            rm0 = fmaxf(rm0, fmaxf(S[nc][0], S[nc][1]));
            rm1 = fmaxf(rm1, fmaxf(S[nc][2], S[nc][3]));
        }
        rm0 = fmaxf(rm0, __shfl_xor_sync(0xffffffffu, rm0, 1));
        rm0 = fmaxf(rm0, __shfl_xor_sync(0xffffffffu, rm0, 2));
        rm1 = fmaxf(rm1, __shfl_xor_sync(0xffffffffu, rm1, 1));
        rm1 = fmaxf(rm1, __shfl_xor_sync(0xffffffffu, rm1, 2));
        float mn0 = fmaxf(m0, rm0), mn1 = fmaxf(m1, rm1);
        float a0 = __expf(m0 - mn0), a1 = __expf(m1 - mn1);
        m0 = mn0; m1 = mn1;
        float s0 = 0.f, s1 = 0.f;
        #pragma unroll
        for (int nc = 0; nc < 8; nc++) {
            S[nc][0] = __expf(S[nc][0] - mn0); s0 += S[nc][0];
            S[nc][1] = __expf(S[nc][1] - mn0); s0 += S[nc][1];
            S[nc][2] = __expf(S[nc][2] - mn1); s1 += S[nc][2];
            S[nc][3] = __expf(S[nc][3] - mn1); s1 += S[nc][3];
        }
        s0 += __shfl_xor_sync(0xffffffffu, s0, 1);
        s0 += __shfl_xor_sync(0xffffffffu, s0, 2);
        s1 += __shfl_xor_sync(0xffffffffu, s1, 1);
        s1 += __shfl_xor_sync(0xffffffffu, s1, 2);
        l0 = l0*a0 + s0;
        l1 = l1*a1 + s1;
        #pragma unroll
        for (int nc = 0; nc < 8; nc++) {
            O[nc][0] *= a0; O[nc][1] *= a0;
            O[nc][2] *= a1; O[nc][3] *= a1;
        }

        // ---- P -> smem fp16 (per-warp-private rows: warp sync only) -------
        #pragma unroll
        for (int nc = 0; nc < 8; nc++) {
            uint32_t p2a = pack_h2(S[nc][0], S[nc][1]);
            int off0 = prow0*128 + (((nc ^ (prow0&7)))<<4) + (lane&3)*4;
            *(uint32_t*)(smc + B_PS + off0) = p2a;
            uint32_t p2b = pack_h2(S[nc][2], S[nc][3]);
            int off1 = (prow0+8)*128 + (((nc ^ ((prow0+8)&7)))<<4) + (lane&3)*4;
            *(uint32_t*)(smc + B_PS + off1) = p2b;
        }
        __syncwarp();

        // ---- O += P V^T (single-term fp16) --------------------------------
        #pragma unroll
        for (int kc = 0; kc < 4; kc++) {
            const int unit = kc*2 + khalf;
            uint32_t ps[4];
            uint32_t aoff = arow*128 + (((unit ^ (arow&7)))<<4);
            ldm4(ps, sb + B_PS + aoff);
            #pragma unroll
            for (int nc2 = 0; nc2 < 4; nc2++) {
                int ch = nc2*16 + lrow;
                uint32_t boff = ch*128 + (((unit ^ (ch&7)))<<4);
                uint32_t bv[4];
                ldm4(bv, sb + B_VS + boff);
                mma16(O[nc2*2],   ps, bv[0], bv[2]);
                mma16(O[nc2*2+1], ps, bv[1], bv[3]);
            }
        }
    }

    // ---- finalize ---------------------------------------------------------
    float inv0 = 1.f / l0, inv1 = 1.f / l1;
    #pragma unroll
    for (int nc = 0; nc < 8; nc++) {
        O[nc][0] *= inv0; O[nc][1] *= inv0;
        O[nc][2] *= inv1; O[nc][3] *= inv1;
    }

    __syncthreads();   // everyone done with Q region
    float* Ost = sm;   // [64 ch][128 row] fp32, aliases Q region (32 KB)
    #pragma unroll
    for (int nc = 0; nc < 8; nc++) {
        int c0 = nc*8 + colb;
        Ost[(c0    )*128 + prow0    ] = O[nc][0];
        Ost[(c0 + 1)*128 + prow0    ] = O[nc][1];
        Ost[(c0    )*128 + prow0 + 8] = O[nc][2];
        Ost[(c0 + 1)*128 + prow0 + 8] = O[nc][3];
    }
    __syncthreads();
    for (int i = tid; i < 8192; i += 256) {
        int c = i >> 7, r = i & 127;
        int gi = (b*CC + c)*NN + n0 + r;
        out[gi] = g * Ost[c*128 + r] + x[gi];
    }
}

// ---------------------------------------------------------------------------
extern "C" void kernel_launch(void* const* d_in, const int* in_sizes, int n_in,
                              void* d_out, int out_size)
{
    const float* c2    = (const float*)d_in[0];
    const float* x     = (const float*)d_in[1];
    const float* w_ea1 = (const float*)d_in[2];
    const float* bn_w  = (const float*)d_in[3];
    const float* bn_b  = (const float*)d_in[4];
    const float* bn_m  = (const float*)d_in[5];
    const float* bn_v  = (const float*)d_in[6];
    const float* w_ea2 = (const float*)d_in[7];
    const float* b_ea2 = (const float*)d_in[8];
    const float* w_q   = (const float*)d_in[9];
    const float* b_q   = (const float*)d_in[10];
    const float* gamma = (const float*)d_in[11];
    float* out = (float*)d_out;

    const int KVEA_SMEM = 64*(65*4 + 129) * (int)sizeof(float);   // 99584 B

    cudaFuncSetAttribute(kvea_kernel, cudaFuncAttributeMaxDynamicSharedMemorySize, KVEA_SMEM);
    cudaFuncSetAttribute(attn_kernel, cudaFuncAttributeMaxDynamicSharedMemorySize, ATTN_SMEM_BYTES);

    pool_kernel<<<(BB*CC*MM + 255)/256, 256>>>(x, c2);
    kvea_kernel<<<dim3(MM/64, BB), 256, KVEA_SMEM>>>(w_ea1, bn_w, bn_b, bn_m,
                                                     bn_v, w_ea2, b_ea2, w_q, b_q);
    q_kernel<<<dim3(NN/64, BB), 256>>>(x, w_q, b_q);
    attn_kernel<<<dim3(NN/128, BB), 256, ATTN_SMEM_BYTES>>>(x, gamma, out);
}

// round 8
// speedup vs baseline: 1.5479x; 1.2034x over previous
#include <cuda_runtime.h>
#include <cuda_fp16.h>
#include <math.h>
#include <stdint.h>

#define BB 4
#define CC 64
#define HH 96
#define WW 96
#define NN (HH*WW)      // 9216
#define HP (HH/2)
#define WP (WW/2)
#define MM (HP*WP)      // 2304
#define KK 64

// Scratch (no allocations allowed)
__device__ __half g_qh[BB*NN*KK];   // q hi, [b][n][d]
__device__ __half g_ql[BB*NN*KK];   // q lo, [b][n][d]
__device__ __half g_kh[BB*MM*KK];   // k hi, [b][m][d]
__device__ __half g_kl[BB*MM*KK];   // k lo, [b][m][d]
__device__ __half g_vh[BB*CC*MM];   // v fp16, [b][c][m]
__device__ float  g_v  [BB*CC*MM];  // pooled x fp32 (kvea input), [b][c][m]
__device__ float  g_c2p[BB*CC*MM];  // pooled c2, [b][c][m]
__device__ float  g_ea [BB*MM];     // sigmoid edge gate, [b][m]

// ---- mma helpers ----------------------------------------------------------
__device__ __forceinline__ void ldm4(uint32_t* r, uint32_t addr) {
    asm volatile("ldmatrix.sync.aligned.m8n8.x4.shared.b16 {%0,%1,%2,%3}, [%4];"
        : "=r"(r[0]), "=r"(r[1]), "=r"(r[2]), "=r"(r[3]) : "r"(addr));
}
__device__ __forceinline__ void mma16(float* d, const uint32_t* a, uint32_t b0, uint32_t b1) {
    asm volatile("mma.sync.aligned.m16n8k16.row.col.f32.f16.f16.f32 "
        "{%0,%1,%2,%3}, {%4,%5,%6,%7}, {%8,%9}, {%0,%1,%2,%3};"
        : "+f"(d[0]), "+f"(d[1]), "+f"(d[2]), "+f"(d[3])
        : "r"(a[0]), "r"(a[1]), "r"(a[2]), "r"(a[3]), "r"(b0), "r"(b1));
}
__device__ __forceinline__ uint32_t smem_u32(const void* p) {
    return (uint32_t)__cvta_generic_to_shared(p);
}
// pack (lo,hi) floats -> f16x2 (elem0 = lo)
__device__ __forceinline__ uint32_t pack_h2(float lo, float hi) {
    uint32_t r; asm("cvt.rn.f16x2.f32 %0, %1, %2;" : "=r"(r) : "f"(hi), "f"(lo)); return r;
}

// smem regions (BYTE offsets), 128B rows, 16B-unit XOR(row&7) swizzle
#define B_QHI 0        // [128 r][64 d] f16 (16 KB)
#define B_QLO 16384    // (16 KB)
#define B_KHI 32768    // [64 key][64 d] f16 (8 KB)
#define B_KLO 40960    // (8 KB)
#define B_VS  49152    // [64 ch][64 key] f16 (8 KB)
#define B_EA  57344    // [64] float
#define ATTN_SMEM_BYTES 57600

// ---------------------------------------------------------------------------
// P0: 2x2 maxpool of x and c2 -> g_v (f32), g_vh (f16), g_c2p. Streaming.
// ---------------------------------------------------------------------------
__global__ void __launch_bounds__(256) pool_kernel(
    const float* __restrict__ x, const float* __restrict__ c2)
{
    int idx = blockIdx.x * 256 + threadIdx.x;
    if (idx >= BB*CC*MM) return;
    int m = idx % MM;
    int bc = idx / MM;            // b*CC + c
    int py = m / WP, px = m % WP;
    int base = (bc*HH + 2*py)*WW + 2*px;
    float2 a0 = *(const float2*)(x + base);
    float2 a1 = *(const float2*)(x + base + WW);
    float vx = fmaxf(fmaxf(a0.x, a0.y), fmaxf(a1.x, a1.y));
    g_v [idx] = vx;
    g_vh[idx] = __float2half_rn(vx);
    float2 b0 = *(const float2*)(c2 + base);
    float2 b1 = *(const float2*)(c2 + base + WW);
    g_c2p[idx] = fmaxf(fmaxf(b0.x, b0.y), fmaxf(b1.x, b1.y));
}

// ---------------------------------------------------------------------------
// P1: on pooled data: k = Wq*xp + bq (fp16 hi/lo, d-contiguous), edge gate ea.
// ---------------------------------------------------------------------------
__global__ void __launch_bounds__(256) kvea_kernel(
    const float* __restrict__ w_ea1, const float* __restrict__ bn_w,
    const float* __restrict__ bn_b,  const float* __restrict__ bn_m,
    const float* __restrict__ bn_v,  const float* __restrict__ w_ea2,
    const float* __restrict__ b_ea2, const float* __restrict__ w_q,
    const float* __restrict__ b_q)
{
    extern __shared__ float sm[];
    float* sWq  = sm;                 // [64][65]
    float* sW1  = sWq  + 64*65;       // [64][129]
    float* sXp  = sW1  + 64*129;      // [64][65]
    float* sC2p = sXp  + 64*65;       // [64][65]
    float* sH   = sC2p + 64*65;       // [64][65]

    const int b   = blockIdx.y;
    const int m0  = blockIdx.x * 64;
    const int tid = threadIdx.x;

    for (int i = tid; i < 64*64;  i += 256) sWq[(i>>6)*65  + (i&63)]  = w_q[i];
    for (int i = tid; i < 64*128; i += 256) sW1[(i>>7)*129 + (i&127)] = w_ea1[i];
    for (int i = tid; i < 4096; i += 256) {
        int c = i >> 6, p = i & 63;
        sXp [p*65 + c] = g_v  [(b*CC + c)*MM + m0 + p];
        sC2p[p*65 + c] = g_c2p[(b*CC + c)*MM + m0 + p];
    }
    __syncthreads();

    for (int job = tid; job < 1024; job += 256) {
        int og = (job >> 6) << 2;
        int p  = job & 63;
        const float* xr = sXp  + p*65;
        const float* cr = sC2p + p*65;
        const float *w0 = sWq + og*65, *w1 = w0+65, *w2 = w0+130, *w3 = w0+195;
        float a0 = b_q[og], a1 = b_q[og+1], a2 = b_q[og+2], a3 = b_q[og+3];
        #pragma unroll 8
        for (int c = 0; c < 64; c++) {
            float xv = xr[c];
            a0 += w0[c]*xv; a1 += w1[c]*xv; a2 += w2[c]*xv; a3 += w3[c]*xv;
        }
        // split to fp16 hi/lo, store d-contiguous [b][m][d]
        {
            __half h0 = __float2half_rn(a0), h1 = __float2half_rn(a1);
            __half h2 = __float2half_rn(a2), h3 = __float2half_rn(a3);
            __half l0h = __float2half_rn(a0 - __half2float(h0));
            __half l1h = __float2half_rn(a1 - __half2float(h1));
            __half l2h = __float2half_rn(a2 - __half2float(h2));
            __half l3h = __float2half_rn(a3 - __half2float(h3));
            size_t base = (size_t)(b*MM + m0 + p)*KK + og;
            __half2 hh0 = __halves2half2(h0, h1), hh1 = __halves2half2(h2, h3);
            __half2 ll0 = __halves2half2(l0h, l1h), ll1 = __halves2half2(l2h, l3h);
            *(uint2*)(g_kh + base) = make_uint2(*(uint32_t*)&hh0, *(uint32_t*)&hh1);
            *(uint2*)(g_kl + base) = make_uint2(*(uint32_t*)&ll0, *(uint32_t*)&ll1);
        }

        const float *u0 = sW1 + og*129, *u1 = u0+129, *u2 = u0+258, *u3 = u0+387;
        float h0=0.f, h1=0.f, h2=0.f, h3=0.f;
        #pragma unroll 8
        for (int c = 0; c < 64; c++) {
            float cv = cr[c];
            h0 += u0[c]*cv; h1 += u1[c]*cv; h2 += u2[c]*cv; h3 += u3[c]*cv;
        }
        #pragma unroll 8
        for (int c = 0; c < 64; c++) {
            float xv = xr[c];
            h0 += u0[64+c]*xv; h1 += u1[64+c]*xv; h2 += u2[64+c]*xv; h3 += u3[64+c]*xv;
        }
        float hh[4] = {h0, h1, h2, h3};
        #pragma unroll
        for (int k2 = 0; k2 < 4; k2++) {
            int o = og + k2;
            float scale = bn_w[o] * rsqrtf(bn_v[o] + 1e-5f);
            float hv = (hh[k2] - bn_m[o]) * scale + bn_b[o];
            sH[p*65 + o] = fmaxf(hv, 0.f);
        }
    }
    __syncthreads();

    if (tid < 64) {
        int p = tid;
        const float* hr = sH + p*65;
        float acc = b_ea2[0];
        #pragma unroll 16
        for (int o = 0; o < 64; o++) acc += w_ea2[o]*hr[o];
        g_ea[b*MM + m0 + p] = 1.f / (1.f + __expf(-acc));
    }
}

// ---------------------------------------------------------------------------
// P2: q = Wq * x + bq, fp16 hi/lo split, d-contiguous [b][n][d]
// ---------------------------------------------------------------------------
__global__ void __launch_bounds__(256) q_kernel(
    const float* __restrict__ x, const float* __restrict__ w_q,
    const float* __restrict__ b_q)
{
    __shared__ float sX [64*65];
    __shared__ float sWq[64*65];
    const int b   = blockIdx.y;
    const int n0  = blockIdx.x * 64;
    const int tid = threadIdx.x;

    for (int i = tid; i < 64*64; i += 256) sWq[(i>>6)*65 + (i&63)] = w_q[i];
    for (int i = tid; i < 64*64; i += 256) {
        int c = i >> 6, p = i & 63;
        sX[p*65 + c] = x[(b*CC + c)*NN + n0 + p];
    }
    __syncthreads();
    for (int job = tid; job < 1024; job += 256) {
        int og = (job >> 6) << 2;
        int p  = job & 63;
        const float* xr = sX + p*65;
        const float *w0 = sWq + og*65, *w1 = w0+65, *w2 = w0+130, *w3 = w0+195;
        float a0 = b_q[og], a1 = b_q[og+1], a2 = b_q[og+2], a3 = b_q[og+3];
        #pragma unroll 8
        for (int c = 0; c < 64; c++) {
            float xv = xr[c];
            a0 += w0[c]*xv; a1 += w1[c]*xv; a2 += w2[c]*xv; a3 += w3[c]*xv;
        }
        __half h0 = __float2half_rn(a0), h1 = __float2half_rn(a1);
        __half h2 = __float2half_rn(a2), h3 = __float2half_rn(a3);
        __half l0h = __float2half_rn(a0 - __half2float(h0));
        __half l1h = __float2half_rn(a1 - __half2float(h1));
        __half l2h = __float2half_rn(a2 - __half2float(h2));
        __half l3h = __float2half_rn(a3 - __half2float(h3));
        size_t base = (size_t)(b*NN + n0 + p)*KK + og;
        __half2 hh0 = __halves2half2(h0, h1), hh1 = __halves2half2(h2, h3);
        __half2 ll0 = __halves2half2(l0h, l1h), ll1 = __halves2half2(l2h, l3h);
        *(uint2*)(g_qh + base) = make_uint2(*(uint32_t*)&hh0, *(uint32_t*)&hh1);
        *(uint2*)(g_ql + base) = make_uint2(*(uint32_t*)&ll0, *(uint32_t*)&ll1);
    }
}

// ---------------------------------------------------------------------------
// A: flash attention, fp16 m16n8k16 mma, P kept in registers (FA2 style).
// QK: 3-term fp16 split. PV: single fp16 (P packed from S accumulators).
// Block = 128 query rows, 8 warps x 16 rows, key tiles of 64. 2 blocks/SM.
// ---------------------------------------------------------------------------
__global__ void __launch_bounds__(256, 2) attn_kernel(
    const float* __restrict__ x, const float* __restrict__ gamma,
    float* __restrict__ out)
{
    extern __shared__ float sm[];
    const uint32_t sb = smem_u32(sm);
    char* smc = (char*)sm;

    const int b    = blockIdx.y;
    const int n0   = blockIdx.x * 128;
    const int tid  = threadIdx.x;
    const int lane = tid & 31;
    const int warp = tid >> 5;
    const int rbase = warp * 16;

    const int lrow  = lane & 15;        // ldmatrix row-in-16
    const int khalf = lane >> 4;        // ldmatrix k-half unit
    const int gid   = lane >> 2;
    const int colb  = 2 * (lane & 3);
    const int prow0 = rbase + gid;
    const int arow  = rbase + lrow;     // A-frag row (Q)

    const float g = gamma[0];

    // ---- load Q block (pre-split fp16), wide swizzled stores --------------
    for (int i = tid; i < 1024; i += 256) {
        int r = i >> 3, u = i & 7;
        size_t gbase = (size_t)(b*NN + n0 + r)*KK + u*8;
        int soff = r*128 + ((u ^ (r&7))<<4);
        *(uint4*)(smc + B_QHI + soff) = *(const uint4*)(g_qh + gbase);
        *(uint4*)(smc + B_QLO + soff) = *(const uint4*)(g_ql + gbase);
    }

    float m0 = -1e30f, m1 = -1e30f, l0 = 0.f, l1 = 0.f;
    float O[8][4];
    #pragma unroll
    for (int nc = 0; nc < 8; nc++)
        #pragma unroll
        for (int j = 0; j < 4; j++) O[nc][j] = 0.f;

    for (int t = 0; t < MM/64; t++) {
        const int mb = t * 64;
        __syncthreads();   // previous tile's K/V reads done
        for (int i = tid; i < 512; i += 256) {
            int j = i >> 3, u = i & 7;
            size_t kb = (size_t)(b*MM + mb + j)*KK + u*8;
            int koff = j*128 + ((u ^ (j&7))<<4);
            *(uint4*)(smc + B_KHI + koff) = *(const uint4*)(g_kh + kb);
            *(uint4*)(smc + B_KLO + koff) = *(const uint4*)(g_kl + kb);
            // V: row j = channel, cols = keys
            size_t vb = (size_t)(b*CC + j)*MM + mb + u*8;
            *(uint4*)(smc + B_VS + koff) = *(const uint4*)(g_vh + vb);
        }
        if (tid < 64) *(float*)(smc + B_EA + tid*4) = g_ea[b*MM + mb + tid];
        __syncthreads();

        // ---- S = Q K^T (3-term fp16 split) --------------------------------
        float S[8][4];
        #pragma unroll
        for (int nc = 0; nc < 8; nc++)
            #pragma unroll
            for (int j = 0; j < 4; j++) S[nc][j] = 0.f;

        #pragma unroll
        for (int kc = 0; kc < 4; kc++) {
            const int unit = kc*2 + khalf;
            uint32_t ah[4], al[4];
            uint32_t aoff = arow*128 + (((unit ^ (arow&7)))<<4);
            ldm4(ah, sb + B_QHI + aoff);
            ldm4(al, sb + B_QLO + aoff);
            #pragma unroll
            for (int nc2 = 0; nc2 < 4; nc2++) {
                int key = nc2*16 + lrow;
                uint32_t boff = key*128 + (((unit ^ (key&7)))<<4);
                uint32_t bh[4];
                ldm4(bh, sb + B_KHI + boff);
                mma16(S[nc2*2],   ah, bh[0], bh[2]);
                mma16(S[nc2*2+1], ah, bh[1], bh[3]);
                mma16(S[nc2*2],   al, bh[0], bh[2]);
                mma16(S[nc2*2+1], al, bh[1], bh[3]);
                uint32_t bl[4];
                ldm4(bl, sb + B_KLO + boff);
                mma16(S[nc2*2],   ah, bl[0], bl[2]);
                mma16(S[nc2*2+1], ah, bl[1], bl[3]);
            }
        }

        // ---- edge gate ----------------------------------------------------
        #pragma unroll
        for (int nc = 0; nc < 8; nc++) {
            float2 e = *(float2*)(smc + B_EA + (nc*8 + colb)*4);
            S[nc][0] *= e.x; S[nc][1] *= e.y;
            S[nc][2] *= e.x; S[nc][3] *= e.y;
        }

        // ---- online softmax ----------------------------------------------
        float rm0 = -1e30f, rm1 = -1e30f;
        #pragma unroll
        for (int nc = 0; nc < 8; nc++) {
            rm0 = fmaxf(rm0, fmaxf(S[nc][0], S[nc][1]));
            rm1 = fmaxf(rm1, fmaxf(S[nc][2], S[nc][3]));
        }
        rm0 = fmaxf(rm0, __shfl_xor_sync(0xffffffffu, rm0, 1));
        rm0 = fmaxf(rm0, __shfl_xor_sync(0xffffffffu, rm0, 2));
        rm1 = fmaxf(rm1, __shfl_xor_sync(0xffffffffu, rm1, 1));
        rm1 = fmaxf(rm1, __shfl_xor_sync(0xffffffffu, rm1, 2));
        float mn0 = fmaxf(m0, rm0), mn1 = fmaxf(m1, rm1);
        float a0 = __expf(m0 - mn0), a1 = __expf(m1 - mn1);
        m0 = mn0; m1 = mn1;
        float s0 = 0.f, s1 = 0.f;
        #pragma unroll
        for (int nc = 0; nc < 8; nc++) {
            S[nc][0] = __expf(S[nc][0] - mn0); s0 += S[nc][0];
            S[nc][1] = __expf(S[nc][1] - mn0); s0 += S[nc][1];
            S[nc][2] = __expf(S[nc][2] - mn1); s1 += S[nc][2];
            S[nc][3] = __expf(S[nc][3] - mn1); s1 += S[nc][3];
        }
        s0 += __shfl_xor_sync(0xffffffffu, s0, 1);
        s0 += __shfl_xor_sync(0xffffffffu, s0, 2);
        s1 += __shfl_xor_sync(0xffffffffu, s1, 1);
        s1 += __shfl_xor_sync(0xffffffffu, s1, 2);
        l0 = l0*a0 + s0;
        l1 = l1*a1 + s1;
        #pragma unroll
        for (int nc = 0; nc < 8; nc++) {
            O[nc][0] *= a0; O[nc][1] *= a0;
            O[nc][2] *= a1; O[nc][3] *= a1;
        }

        // ---- pack P into A-fragment registers (no smem round trip) --------
        uint32_t pk[16];
        #pragma unroll
        for (int nc = 0; nc < 8; nc++) {
            pk[nc*2    ] = pack_h2(S[nc][0], S[nc][1]);   // row gid
            pk[nc*2 + 1] = pack_h2(S[nc][2], S[nc][3]);   // row gid+8
        }

        // ---- O += P V^T (P from registers) --------------------------------
        #pragma unroll
        for (int kc2 = 0; kc2 < 4; kc2++) {
            const int unit = kc2*2 + khalf;
            const uint32_t* a = pk + kc2*4;   // {a0,a1,a2,a3} A-fragment
            #pragma unroll
            for (int nc2 = 0; nc2 < 4; nc2++) {
                int ch = nc2*16 + lrow;
                uint32_t boff = ch*128 + (((unit ^ (ch&7)))<<4);
                uint32_t bv[4];
                ldm4(bv, sb + B_VS + boff);
                mma16(O[nc2*2],   a, bv[0], bv[2]);
                mma16(O[nc2*2+1], a, bv[1], bv[3]);
            }
        }
    }

    // ---- finalize ---------------------------------------------------------
    float inv0 = 1.f / l0, inv1 = 1.f / l1;
    #pragma unroll
    for (int nc = 0; nc < 8; nc++) {
        O[nc][0] *= inv0; O[nc][1] *= inv0;
        O[nc][2] *= inv1; O[nc][3] *= inv1;
    }

    __syncthreads();   // everyone done with Q region
    float* Ost = sm;   // [64 ch][128 row] fp32 (32 KB), aliases Q regions
    #pragma unroll
    for (int nc = 0; nc < 8; nc++) {
        int c0 = nc*8 + colb;
        Ost[(c0    )*128 + prow0    ] = O[nc][0];
        Ost[(c0 + 1)*128 + prow0    ] = O[nc][1];
        Ost[(c0    )*128 + prow0 + 8] = O[nc][2];
        Ost[(c0 + 1)*128 + prow0 + 8] = O[nc][3];
    }
    __syncthreads();
    for (int i = tid; i < 8192; i += 256) {
        int c = i >> 7, r = i & 127;
        int gi = (b*CC + c)*NN + n0 + r;
        out[gi] = g * Ost[c*128 + r] + x[gi];
    }
}

// ---------------------------------------------------------------------------
extern "C" void kernel_launch(void* const* d_in, const int* in_sizes, int n_in,
                              void* d_out, int out_size)
{
    const float* c2    = (const float*)d_in[0];
    const float* x     = (const float*)d_in[1];
    const float* w_ea1 = (const float*)d_in[2];
    const float* bn_w  = (const float*)d_in[3];
    const float* bn_b  = (const float*)d_in[4];
    const float* bn_m  = (const float*)d_in[5];
    const float* bn_v  = (const float*)d_in[6];
    const float* w_ea2 = (const float*)d_in[7];
    const float* b_ea2 = (const float*)d_in[8];
    const float* w_q   = (const float*)d_in[9];
    const float* b_q   = (const float*)d_in[10];
    const float* gamma = (const float*)d_in[11];
    float* out = (float*)d_out;

    const int KVEA_SMEM = 64*(65*4 + 129) * (int)sizeof(float);   // 99584 B

    cudaFuncSetAttribute(kvea_kernel, cudaFuncAttributeMaxDynamicSharedMemorySize, KVEA_SMEM);
    cudaFuncSetAttribute(attn_kernel, cudaFuncAttributeMaxDynamicSharedMemorySize, ATTN_SMEM_BYTES);

    pool_kernel<<<(BB*CC*MM + 255)/256, 256>>>(x, c2);
    kvea_kernel<<<dim3(MM/64, BB), 256, KVEA_SMEM>>>(w_ea1, bn_w, bn_b, bn_m,
                                                     bn_v, w_ea2, b_ea2, w_q, b_q);
    q_kernel<<<dim3(NN/64, BB), 256>>>(x, w_q, b_q);
    attn_kernel<<<dim3(NN/128, BB), 256, ATTN_SMEM_BYTES>>>(x, gamma, out);
}

// round 9
// speedup vs baseline: 1.7145x; 1.1077x over previous
#include <cuda_runtime.h>
#include <cuda_fp16.h>
#include <math.h>
#include <stdint.h>

#define BB 4
#define CC 64
#define HH 96
#define WW 96
#define NN (HH*WW)      // 9216
#define HP (HH/2)
#define WP (WW/2)
#define MM (HP*WP)      // 2304
#define KK 64

// Scratch (no allocations allowed)
__device__ __align__(16) __half g_xh[BB*NN*KK];   // x hi, [b][n][c]
__device__ __align__(16) __half g_xl[BB*NN*KK];   // x lo, [b][n][c]
__device__ __align__(16) __half g_uh[BB*MM*KK];   // u'=ea*G*xp hi, [b][m][d]
__device__ __align__(16) __half g_ul[BB*MM*KK];   // u' lo, [b][m][d]
__device__ __align__(16) __half g_vh[BB*CC*MM];   // v fp16, [b][c][m]
__device__ __align__(16) float  g_v  [BB*CC*MM];  // pooled x fp32, [b][c][m]
__device__ __align__(16) float  g_c2p[BB*CC*MM];  // pooled c2, [b][c][m]
__device__ __align__(16) float  g_cm [BB*MM];     // ea*(alpha+bb), [b][m]
__device__ __align__(16) float  g_eam[BB*MM];     // ea, [b][m]
__device__ __align__(16) float  g_beta[BB*NN];    // wb . x_n, [b][n]
__device__ float g_G [64*64];    // Wq^T Wq
__device__ float g_wb[64];       // b_q^T Wq
__device__ float g_bb[1];        // |b_q|^2

// ---- mma / async helpers --------------------------------------------------
__device__ __forceinline__ void ldm4(uint32_t* r, uint32_t addr) {
    asm volatile("ldmatrix.sync.aligned.m8n8.x4.shared.b16 {%0,%1,%2,%3}, [%4];"
        : "=r"(r[0]), "=r"(r[1]), "=r"(r[2]), "=r"(r[3]) : "r"(addr));
}
__device__ __forceinline__ void mma16(float* d, const uint32_t* a, uint32_t b0, uint32_t b1) {
    asm volatile("mma.sync.aligned.m16n8k16.row.col.f32.f16.f16.f32 "
        "{%0,%1,%2,%3}, {%4,%5,%6,%7}, {%8,%9}, {%0,%1,%2,%3};"
        : "+f"(d[0]), "+f"(d[1]), "+f"(d[2]), "+f"(d[3])
        : "r"(a[0]), "r"(a[1]), "r"(a[2]), "r"(a[3]), "r"(b0), "r"(b1));
}
__device__ __forceinline__ uint32_t smem_u32(const void* p) {
    return (uint32_t)__cvta_generic_to_shared(p);
}
__device__ __forceinline__ uint32_t pack_h2(float lo, float hi) {
    uint32_t r; asm("cvt.rn.f16x2.f32 %0, %1, %2;" : "=r"(r) : "f"(hi), "f"(lo)); return r;
}
__device__ __forceinline__ void cpa16(uint32_t s, const void* g) {
    asm volatile("cp.async.cg.shared.global [%0], [%1], 16;" :: "r"(s), "l"(g));
}
#define CPA_COMMIT() asm volatile("cp.async.commit_group;" ::: "memory")
#define CPA_WAIT0()  asm volatile("cp.async.wait_group 0;"  ::: "memory")

// attn smem layout (bytes)
#define B_XHI 0                       // [128 r][64 c] f16 (16 KB)
#define B_XLO 16384
#define B_ST(s) (32768 + (s)*25088)   // per-stage: UH +0, UL +8192, VS +16384,
#define ST_UH 0                       //            CM +24576, EAM +24832
#define ST_UL 8192
#define ST_VS 16384
#define ST_CM 24576
#define ST_EAM 24832
#define B_BETA 82944                  // [128] float
#define ATTN_SMEM_BYTES 83456

// ---------------------------------------------------------------------------
// G0: G = Wq^T Wq, wb = b^T Wq, bb = |b|^2. One block.
// ---------------------------------------------------------------------------
__global__ void __launch_bounds__(256) gmat_kernel(
    const float* __restrict__ w_q, const float* __restrict__ b_q)
{
    __shared__ float sW[64*65];
    const int tid = threadIdx.x;
    for (int i = tid; i < 4096; i += 256) sW[(i>>6)*65 + (i&63)] = w_q[i];
    __syncthreads();
    for (int i = tid; i < 4096; i += 256) {
        int c1 = i >> 6, c2 = i & 63;
        float acc = 0.f;
        #pragma unroll 8
        for (int k = 0; k < 64; k++) acc += sW[k*65 + c1] * sW[k*65 + c2];
        g_G[i] = acc;
    }
    if (tid < 64) {
        float acc = 0.f;
        #pragma unroll 8
        for (int k = 0; k < 64; k++) acc += b_q[k] * sW[k*65 + tid];
        g_wb[tid] = acc;
    }
    if (tid == 0) {
        float acc = 0.f;
        for (int k = 0; k < 64; k++) acc += b_q[k]*b_q[k];
        g_bb[0] = acc;
    }
}

// ---------------------------------------------------------------------------
// P0: 2x2 maxpool of x and c2. Streaming.
// ---------------------------------------------------------------------------
__global__ void __launch_bounds__(256) pool_kernel(
    const float* __restrict__ x, const float* __restrict__ c2)
{
    int idx = blockIdx.x * 256 + threadIdx.x;
    if (idx >= BB*CC*MM) return;
    int m = idx % MM;
    int bc = idx / MM;
    int py = m / WP, px = m % WP;
    int base = (bc*HH + 2*py)*WW + 2*px;
    float2 a0 = *(const float2*)(x + base);
    float2 a1 = *(const float2*)(x + base + WW);
    float vx = fmaxf(fmaxf(a0.x, a0.y), fmaxf(a1.x, a1.y));
    g_v [idx] = vx;
    g_vh[idx] = __float2half_rn(vx);
    float2 b0 = *(const float2*)(c2 + base);
    float2 b1 = *(const float2*)(c2 + base + WW);
    g_c2p[idx] = fmaxf(fmaxf(b0.x, b0.y), fmaxf(b1.x, b1.y));
}

// ---------------------------------------------------------------------------
// P1: transpose+split x -> g_xh/g_xl [b][n][c], beta_n = wb . x_n
// ---------------------------------------------------------------------------
__global__ void __launch_bounds__(256) xsplit_kernel(const float* __restrict__ x)
{
    __shared__ float sX [64*65];
    __shared__ float swb[64];
    const int b   = blockIdx.y;
    const int n0  = blockIdx.x * 64;
    const int tid = threadIdx.x;

    if (tid < 64) swb[tid] = g_wb[tid];
    for (int i = tid; i < 4096; i += 256) {
        int c = i >> 6, p = i & 63;
        sX[p*65 + c] = x[(b*CC + c)*NN + n0 + p];
    }
    __syncthreads();

    if (tid < 64) {
        const float* xr = sX + tid*65;
        float acc = 0.f;
        #pragma unroll 8
        for (int c = 0; c < 64; c++) acc += swb[c]*xr[c];
        g_beta[b*NN + n0 + tid] = acc;
    }
    for (int i = tid; i < 2048; i += 256) {
        int p = i >> 5, c0 = (i & 31)*2;
        float f0 = sX[p*65 + c0], f1 = sX[p*65 + c0 + 1];
        __half h0 = __float2half_rn(f0), h1 = __float2half_rn(f1);
        __half l0 = __float2half_rn(f0 - __half2float(h0));
        __half l1 = __float2half_rn(f1 - __half2float(h1));
        size_t base = (size_t)(b*NN + n0 + p)*KK + c0;
        *(__half2*)(g_xh + base) = __halves2half2(h0, h1);
        *(__half2*)(g_xl + base) = __halves2half2(l0, l1);
    }
}

// ---------------------------------------------------------------------------
// P2: kvea: ea gate, then u' = ea*(G xp) split fp16, cm = ea*(alpha+bb)
// ---------------------------------------------------------------------------
__global__ void __launch_bounds__(256) kvea_kernel(
    const float* __restrict__ w_ea1, const float* __restrict__ bn_w,
    const float* __restrict__ bn_b,  const float* __restrict__ bn_m,
    const float* __restrict__ bn_v,  const float* __restrict__ w_ea2,
    const float* __restrict__ b_ea2)
{
    extern __shared__ float sm[];
    float* sG   = sm;                 // [64][65]
    float* sW1  = sG   + 64*65;       // [64][129]
    float* sXp  = sW1  + 64*129;      // [64][65]
    float* sC2p = sXp  + 64*65;       // [64][65]
    float* sH   = sC2p + 64*65;       // [64][65]
    float* sEA  = sH   + 64*65;       // [64]
    float* swb  = sEA  + 64;          // [64]

    const int b   = blockIdx.y;
    const int m0  = blockIdx.x * 64;
    const int tid = threadIdx.x;

    for (int i = tid; i < 64*64;  i += 256) sG[(i>>6)*65  + (i&63)]  = g_G[i];
    for (int i = tid; i < 64*128; i += 256) sW1[(i>>7)*129 + (i&127)] = w_ea1[i];
    if (tid < 64) swb[tid] = g_wb[tid];
    for (int i = tid; i < 4096; i += 256) {
        int c = i >> 6, p = i & 63;
        sXp [p*65 + c] = g_v  [(b*CC + c)*MM + m0 + p];
        sC2p[p*65 + c] = g_c2p[(b*CC + c)*MM + m0 + p];
    }
    __syncthreads();

    // hidden layer h (4-way ILP)
    for (int job = tid; job < 1024; job += 256) {
        int og = (job >> 6) << 2;
        int p  = job & 63;
        const float* xr = sXp  + p*65;
        const float* cr = sC2p + p*65;
        const float *u0 = sW1 + og*129, *u1 = u0+129, *u2 = u0+258, *u3 = u0+387;
        float h0=0.f, h1=0.f, h2=0.f, h3=0.f;
        #pragma unroll 8
        for (int c = 0; c < 64; c++) {
            float cv = cr[c];
            h0 += u0[c]*cv; h1 += u1[c]*cv; h2 += u2[c]*cv; h3 += u3[c]*cv;
        }
        #pragma unroll 8
        for (int c = 0; c < 64; c++) {
            float xv = xr[c];
            h0 += u0[64+c]*xv; h1 += u1[64+c]*xv; h2 += u2[64+c]*xv; h3 += u3[64+c]*xv;
        }
        float hh[4] = {h0, h1, h2, h3};
        #pragma unroll
        for (int k2 = 0; k2 < 4; k2++) {
            int o = og + k2;
            float scale = bn_w[o] * rsqrtf(bn_v[o] + 1e-5f);
            float hv = (hh[k2] - bn_m[o]) * scale + bn_b[o];
            sH[p*65 + o] = fmaxf(hv, 0.f);
        }
    }
    __syncthreads();

    if (tid < 64) {
        int p = tid;
        const float* hr = sH + p*65;
        const float* xr = sXp + p*65;
        float acc = b_ea2[0], alpha = 0.f;
        #pragma unroll 8
        for (int o = 0; o < 64; o++) { acc += w_ea2[o]*hr[o]; alpha += swb[o]*xr[o]; }
        float ea = 1.f / (1.f + __expf(-acc));
        sEA[p] = ea;
        g_eam[b*MM + m0 + p] = ea;
        g_cm [b*MM + m0 + p] = ea * (alpha + g_bb[0]);
    }
    __syncthreads();

    // u' = ea * (G xp), split fp16 hi/lo, d-contiguous [b][m][d]
    for (int job = tid; job < 1024; job += 256) {
        int og = (job >> 6) << 2;
        int p  = job & 63;
        const float* xr = sXp + p*65;
        const float *w0 = sG + og*65, *w1 = w0+65, *w2 = w0+130, *w3 = w0+195;
        float a0=0.f, a1=0.f, a2=0.f, a3=0.f;
        #pragma unroll 8
        for (int c = 0; c < 64; c++) {
            float xv = xr[c];
            a0 += w0[c]*xv; a1 += w1[c]*xv; a2 += w2[c]*xv; a3 += w3[c]*xv;
        }
        float ea = sEA[p];
        a0 *= ea; a1 *= ea; a2 *= ea; a3 *= ea;
        __half h0 = __float2half_rn(a0), h1 = __float2half_rn(a1);
        __half h2 = __float2half_rn(a2), h3 = __float2half_rn(a3);
        __half l0 = __float2half_rn(a0 - __half2float(h0));
        __half l1 = __float2half_rn(a1 - __half2float(h1));
        __half l2 = __float2half_rn(a2 - __half2float(h2));
        __half l3 = __float2half_rn(a3 - __half2float(h3));
        size_t base = (size_t)(b*MM + m0 + p)*KK + og;
        __half2 hh0 = __halves2half2(h0, h1), hh1 = __halves2half2(h2, h3);
        __half2 ll0 = __halves2half2(l0, l1), ll1 = __halves2half2(l2, l3);
        *(uint2*)(g_uh + base) = make_uint2(*(uint32_t*)&hh0, *(uint32_t*)&hh1);
        *(uint2*)(g_ul + base) = make_uint2(*(uint32_t*)&ll0, *(uint32_t*)&ll1);
    }
}

// ---------------------------------------------------------------------------
// A: flash attention on x vs u', cp.async double-buffered tiles.
// logit = x.u' + cm_col + beta_row*ea_col; P in registers (FA2 style).
// ---------------------------------------------------------------------------
__global__ void __launch_bounds__(256, 2) attn_kernel(
    const float* __restrict__ x, const float* __restrict__ gamma,
    float* __restrict__ out)
{
    extern __shared__ float sm[];
    const uint32_t sb = smem_u32(sm);
    char* smc = (char*)sm;

    const int b    = blockIdx.y;
    const int n0   = blockIdx.x * 128;
    const int tid  = threadIdx.x;
    const int lane = tid & 31;
    const int warp = tid >> 5;
    const int rbase = warp * 16;

    const int lrow  = lane & 15;
    const int khalf = lane >> 4;
    const int gid   = lane >> 2;
    const int colb  = 2 * (lane & 3);
    const int prow0 = rbase + gid;
    const int arow  = rbase + lrow;

    const float g = gamma[0];

    // ---- load X block (pre-split) + beta ----------------------------------
    for (int i = tid; i < 1024; i += 256) {
        int r = i >> 3, u = i & 7;
        size_t gbase = (size_t)(b*NN + n0 + r)*KK + u*8;
        int soff = r*128 + ((u ^ (r&7))<<4);
        *(uint4*)(smc + B_XHI + soff) = *(const uint4*)(g_xh + gbase);
        *(uint4*)(smc + B_XLO + soff) = *(const uint4*)(g_xl + gbase);
    }
    if (tid < 32) *(uint4*)(smc + B_BETA + tid*16) =
        *(const uint4*)(g_beta + b*NN + n0 + tid*4);
    __syncthreads();
    const float beta0 = *(float*)(smc + B_BETA + prow0*4);
    const float beta1 = *(float*)(smc + B_BETA + (prow0+8)*4);

    // ---- prologue: async-load tile 0 into stage 0 -------------------------
    {
        const int mb = 0, s = 0;
        for (int i = tid; i < 512; i += 256) {
            int j = i >> 3, u = i & 7;
            int koff = j*128 + ((u ^ (j&7))<<4);
            size_t kb = (size_t)(b*MM + mb + j)*KK + u*8;
            cpa16(sb + B_ST(s) + ST_UH + koff, g_uh + kb);
            cpa16(sb + B_ST(s) + ST_UL + koff, g_ul + kb);
            size_t vb = (size_t)(b*CC + j)*MM + mb + u*8;
            cpa16(sb + B_ST(s) + ST_VS + koff, g_vh + vb);
        }
        if (tid < 16)      cpa16(sb + B_ST(s) + ST_CM  + tid*16,      g_cm  + b*MM + mb + tid*4);
        else if (tid < 32) cpa16(sb + B_ST(s) + ST_EAM + (tid-16)*16, g_eam + b*MM + mb + (tid-16)*4);
        CPA_COMMIT();
    }

    float m0 = -1e30f, m1 = -1e30f, l0 = 0.f, l1 = 0.f;
    float O[8][4];
    #pragma unroll
    for (int nc = 0; nc < 8; nc++)
        #pragma unroll
        for (int j = 0; j < 4; j++) O[nc][j] = 0.f;

    for (int t = 0; t < MM/64; t++) {
        const int cur = t & 1;
        CPA_WAIT0();
        __syncthreads();   // tile t landed AND all warps done with stage cur

        // prefetch tile t+1 into the other stage (read last during tile t-1)
        if (t + 1 < MM/64) {
            const int mb2 = (t+1) * 64, s = cur ^ 1;
            for (int i = tid; i < 512; i += 256) {
                int j = i >> 3, u = i & 7;
                int koff = j*128 + ((u ^ (j&7))<<4);
                size_t kb = (size_t)(b*MM + mb2 + j)*KK + u*8;
                cpa16(sb + B_ST(s) + ST_UH + koff, g_uh + kb);
                cpa16(sb + B_ST(s) + ST_UL + koff, g_ul + kb);
                size_t vb = (size_t)(b*CC + j)*MM + mb2 + u*8;
                cpa16(sb + B_ST(s) + ST_VS + koff, g_vh + vb);
            }
            if (tid < 16)      cpa16(sb + B_ST(s) + ST_CM  + tid*16,      g_cm  + b*MM + mb2 + tid*4);
            else if (tid < 32) cpa16(sb + B_ST(s) + ST_EAM + (tid-16)*16, g_eam + b*MM + mb2 + (tid-16)*4);
            CPA_COMMIT();
        }

        const uint32_t sbK = sb + B_ST(cur);
        char* stc = smc + B_ST(cur);

        // ---- S = X U'^T (3-term fp16 split) -------------------------------
        float S[8][4];
        #pragma unroll
        for (int nc = 0; nc < 8; nc++)
            #pragma unroll
            for (int j = 0; j < 4; j++) S[nc][j] = 0.f;

        #pragma unroll
        for (int kc = 0; kc < 4; kc++) {
            const int unit = kc*2 + khalf;
            uint32_t ah[4], al[4];
            uint32_t aoff = arow*128 + (((unit ^ (arow&7)))<<4);
            ldm4(ah, sb + B_XHI + aoff);
            ldm4(al, sb + B_XLO + aoff);
            #pragma unroll
            for (int nc2 = 0; nc2 < 4; nc2++) {
                int key = nc2*16 + lrow;
                uint32_t boff = key*128 + (((unit ^ (key&7)))<<4);
                uint32_t bh[4];
                ldm4(bh, sbK + ST_UH + boff);
                mma16(S[nc2*2],   ah, bh[0], bh[2]);
                mma16(S[nc2*2+1], ah, bh[1], bh[3]);
                mma16(S[nc2*2],   al, bh[0], bh[2]);
                mma16(S[nc2*2+1], al, bh[1], bh[3]);
                uint32_t bl[4];
                ldm4(bl, sbK + ST_UL + boff);
                mma16(S[nc2*2],   ah, bl[0], bl[2]);
                mma16(S[nc2*2+1], ah, bl[1], bl[3]);
            }
        }

        // ---- bias terms: + cm_col + beta_row*ea_col -----------------------
        #pragma unroll
        for (int nc = 0; nc < 8; nc++) {
            float2 cm2 = *(float2*)(stc + ST_CM  + (nc*8 + colb)*4);
            float2 em2 = *(float2*)(stc + ST_EAM + (nc*8 + colb)*4);
            S[nc][0] += cm2.x + beta0*em2.x;
            S[nc][1] += cm2.y + beta0*em2.y;
            S[nc][2] += cm2.x + beta1*em2.x;
            S[nc][3] += cm2.y + beta1*em2.y;
        }

        // ---- online softmax ----------------------------------------------
        float rm0 = -1e30f, rm1 = -1e30f;
        #pragma unroll
        for (int nc = 0; nc < 8; nc++) {
            rm0 = fmaxf(rm0, fmaxf(S[nc][0], S[nc][1]));
            rm1 = fmaxf(rm1, fmaxf(S[nc][2], S[nc][3]));
        }
        rm0 = fmaxf(rm0, __shfl_xor_sync(0xffffffffu, rm0, 1));
        rm0 = fmaxf(rm0, __shfl_xor_sync(0xffffffffu, rm0, 2));
        rm1 = fmaxf(rm1, __shfl_xor_sync(0xffffffffu, rm1, 1));
        rm1 = fmaxf(rm1, __shfl_xor_sync(0xffffffffu, rm1, 2));
        float mn0 = fmaxf(m0, rm0), mn1 = fmaxf(m1, rm1);
        float a0 = __expf(m0 - mn0), a1 = __expf(m1 - mn1);
        m0 = mn0; m1 = mn1;
        float s0 = 0.f, s1 = 0.f;
        #pragma unroll
        for (int nc = 0; nc < 8; nc++) {
            S[nc][0] = __expf(S[nc][0] - mn0); s0 += S[nc][0];
            S[nc][1] = __expf(S[nc][1] - mn0); s0 += S[nc][1];
            S[nc][2] = __expf(S[nc][2] - mn1); s1 += S[nc][2];
            S[nc][3] = __expf(S[nc][3] - mn1); s1 += S[nc][3];
        }
        s0 += __shfl_xor_sync(0xffffffffu, s0, 1);
        s0 += __shfl_xor_sync(0xffffffffu, s0, 2);
        s1 += __shfl_xor_sync(0xffffffffu, s1, 1);
        s1 += __shfl_xor_sync(0xffffffffu, s1, 2);
        l0 = l0*a0 + s0;
        l1 = l1*a1 + s1;
        #pragma unroll
        for (int nc = 0; nc < 8; nc++) {
            O[nc][0] *= a0; O[nc][1] *= a0;
            O[nc][2] *= a1; O[nc][3] *= a1;
        }

        // ---- pack P into A-fragments (registers) --------------------------
        uint32_t pk[16];
        #pragma unroll
        for (int nc = 0; nc < 8; nc++) {
            pk[nc*2    ] = pack_h2(S[nc][0], S[nc][1]);
            pk[nc*2 + 1] = pack_h2(S[nc][2], S[nc][3]);
        }

        // ---- O += P V^T ---------------------------------------------------
        #pragma unroll
        for (int kc2 = 0; kc2 < 4; kc2++) {
            const int unit = kc2*2 + khalf;
            const uint32_t* a = pk + kc2*4;
            #pragma unroll
            for (int nc2 = 0; nc2 < 4; nc2++) {
                int ch = nc2*16 + lrow;
                uint32_t boff = ch*128 + (((unit ^ (ch&7)))<<4);
                uint32_t bv[4];
                ldm4(bv, sbK + ST_VS + boff);
                mma16(O[nc2*2],   a, bv[0], bv[2]);
                mma16(O[nc2*2+1], a, bv[1], bv[3]);
            }
        }
    }

    // ---- finalize ---------------------------------------------------------
    float inv0 = 1.f / l0, inv1 = 1.f / l1;
    #pragma unroll
    for (int nc = 0; nc < 8; nc++) {
        O[nc][0] *= inv0; O[nc][1] *= inv0;
        O[nc][2] *= inv1; O[nc][3] *= inv1;
    }

    __syncthreads();
    float* Ost = sm;   // [64 ch][128 row] fp32 (32 KB), aliases X regions
    #pragma unroll
    for (int nc = 0; nc < 8; nc++) {
        int c0 = nc*8 + colb;
        Ost[(c0    )*128 + prow0    ] = O[nc][0];
        Ost[(c0 + 1)*128 + prow0    ] = O[nc][1];
        Ost[(c0    )*128 + prow0 + 8] = O[nc][2];
        Ost[(c0 + 1)*128 + prow0 + 8] = O[nc][3];
    }
    __syncthreads();
    for (int i = tid; i < 8192; i += 256) {
        int c = i >> 7, r = i & 127;
        int gi = (b*CC + c)*NN + n0 + r;
        out[gi] = g * Ost[c*128 + r] + x[gi];
    }
}

// ---------------------------------------------------------------------------
extern "C" void kernel_launch(void* const* d_in, const int* in_sizes, int n_in,
                              void* d_out, int out_size)
{
    const float* c2    = (const float*)d_in[0];
    const float* x     = (const float*)d_in[1];
    const float* w_ea1 = (const float*)d_in[2];
    const float* bn_w  = (const float*)d_in[3];
    const float* bn_b  = (const float*)d_in[4];
    const float* bn_m  = (const float*)d_in[5];
    const float* bn_v  = (const float*)d_in[6];
    const float* w_ea2 = (const float*)d_in[7];
    const float* b_ea2 = (const float*)d_in[8];
    const float* w_q   = (const float*)d_in[9];
    const float* b_q   = (const float*)d_in[10];
    const float* gamma = (const float*)d_in[11];
    float* out = (float*)d_out;

    const int KVEA_SMEM = (64*65*4 + 64*129 + 128) * (int)sizeof(float);   // 99840 B

    cudaFuncSetAttribute(kvea_kernel, cudaFuncAttributeMaxDynamicSharedMemorySize, KVEA_SMEM);
    cudaFuncSetAttribute(attn_kernel, cudaFuncAttributeMaxDynamicSharedMemorySize, ATTN_SMEM_BYTES);

    gmat_kernel<<<1, 256>>>(w_q, b_q);
    pool_kernel<<<(BB*CC*MM + 255)/256, 256>>>(x, c2);
    xsplit_kernel<<<dim3(NN/64, BB), 256>>>(x);
    kvea_kernel<<<dim3(MM/64, BB), 256, KVEA_SMEM>>>(w_ea1, bn_w, bn_b, bn_m,
                                                     bn_v, w_ea2, b_ea2);
    attn_kernel<<<dim3(NN/128, BB), 256, ATTN_SMEM_BYTES>>>(x, gamma, out);
}

// round 10
// speedup vs baseline: 1.8037x; 1.0520x over previous
#include <cuda_runtime.h>
#include <cuda_fp16.h>
#include <math.h>
#include <stdint.h>

#define BB 4
#define CC 64
#define HH 96
#define WW 96
#define NN (HH*WW)      // 9216
#define HP (HH/2)
#define WP (WW/2)
#define MM (HP*WP)      // 2304
#define KK 64

// Scratch (no allocations allowed)
__device__ __align__(16) __half g_xh[BB*NN*KK];   // x hi, [b][n][c]
__device__ __align__(16) __half g_xl[BB*NN*KK];   // x lo, [b][n][c]
__device__ __align__(16) __half g_uh[BB*MM*KK];   // u'=ea*G*xp hi, [b][m][d]
__device__ __align__(16) __half g_ul[BB*MM*KK];   // u' lo, [b][m][d]
__device__ __align__(16) __half g_vh[BB*CC*MM];   // v fp16, [b][c][m]
__device__ __align__(16) float  g_v  [BB*CC*MM];  // pooled x fp32, [b][c][m]
__device__ __align__(16) float  g_c2p[BB*CC*MM];  // pooled c2, [b][c][m]
__device__ __align__(16) float  g_cm [BB*MM];     // ea*(alpha+bb), [b][m]
__device__ __align__(16) float  g_eam[BB*MM];     // ea, [b][m]
__device__ __align__(16) float  g_beta[BB*NN];    // wb . x_n, [b][n]
__device__ __align__(16) float g_G [64*64];  // Wq^T Wq (symmetric)
__device__ float g_wb[64];                   // b_q^T Wq
__device__ float g_bb[1];                    // |b_q|^2

// ---- mma / async helpers --------------------------------------------------
__device__ __forceinline__ void ldm4(uint32_t* r, uint32_t addr) {
    asm volatile("ldmatrix.sync.aligned.m8n8.x4.shared.b16 {%0,%1,%2,%3}, [%4];"
        : "=r"(r[0]), "=r"(r[1]), "=r"(r[2]), "=r"(r[3]) : "r"(addr));
}
__device__ __forceinline__ void mma16(float* d, const uint32_t* a, uint32_t b0, uint32_t b1) {
    asm volatile("mma.sync.aligned.m16n8k16.row.col.f32.f16.f16.f32 "
        "{%0,%1,%2,%3}, {%4,%5,%6,%7}, {%8,%9}, {%0,%1,%2,%3};"
        : "+f"(d[0]), "+f"(d[1]), "+f"(d[2]), "+f"(d[3])
        : "r"(a[0]), "r"(a[1]), "r"(a[2]), "r"(a[3]), "r"(b0), "r"(b1));
}
__device__ __forceinline__ uint32_t smem_u32(const void* p) {
    return (uint32_t)__cvta_generic_to_shared(p);
}
__device__ __forceinline__ uint32_t pack_h2(float lo, float hi) {
    uint32_t r; asm("cvt.rn.f16x2.f32 %0, %1, %2;" : "=r"(r) : "f"(hi), "f"(lo)); return r;
}
__device__ __forceinline__ void cpa16(uint32_t s, const void* g) {
    asm volatile("cp.async.cg.shared.global [%0], [%1], 16;" :: "r"(s), "l"(g));
}
#define CPA_COMMIT() asm volatile("cp.async.commit_group;" ::: "memory")
#define CPA_WAIT0()  asm volatile("cp.async.wait_group 0;"  ::: "memory")

// attn smem layout (bytes)
#define B_XHI 0                       // [128 r][64 c] f16 (16 KB)
#define B_XLO 16384
#define B_ST(s) (32768 + (s)*25088)   // per-stage: UH +0, UL +8192, VS +16384,
#define ST_UH 0                       //            CM +24576, EAM +24832
#define ST_UL 8192
#define ST_VS 16384
#define ST_CM 24576
#define ST_EAM 24832
#define B_BETA 82944                  // [128] float
#define ATTN_SMEM_BYTES 83456

// ---------------------------------------------------------------------------
// G0: G = Wq^T Wq, wb = b^T Wq, bb = |b|^2. One block.
// ---------------------------------------------------------------------------
__global__ void __launch_bounds__(256) gmat_kernel(
    const float* __restrict__ w_q, const float* __restrict__ b_q)
{
    __shared__ float sW[64*65];
    const int tid = threadIdx.x;
    for (int i = tid; i < 4096; i += 256) sW[(i>>6)*65 + (i&63)] = w_q[i];
    __syncthreads();
    for (int i = tid; i < 4096; i += 256) {
        int c1 = i >> 6, c2 = i & 63;
        float acc = 0.f;
        #pragma unroll 8
        for (int k = 0; k < 64; k++) acc += sW[k*65 + c1] * sW[k*65 + c2];
        g_G[i] = acc;
    }
    if (tid < 64) {
        float acc = 0.f;
        #pragma unroll 8
        for (int k = 0; k < 64; k++) acc += b_q[k] * sW[k*65 + tid];
        g_wb[tid] = acc;
    }
    if (tid == 0) {
        float acc = 0.f;
        for (int k = 0; k < 64; k++) acc += b_q[k]*b_q[k];
        g_bb[0] = acc;
    }
}

// ---------------------------------------------------------------------------
// P0: 2x2 maxpool of x and c2. Streaming.
// ---------------------------------------------------------------------------
__global__ void __launch_bounds__(256) pool_kernel(
    const float* __restrict__ x, const float* __restrict__ c2)
{
    int idx = blockIdx.x * 256 + threadIdx.x;
    if (idx >= BB*CC*MM) return;
    int m = idx % MM;
    int bc = idx / MM;
    int py = m / WP, px = m % WP;
    int base = (bc*HH + 2*py)*WW + 2*px;
    float2 a0 = *(const float2*)(x + base);
    float2 a1 = *(const float2*)(x + base + WW);
    float vx = fmaxf(fmaxf(a0.x, a0.y), fmaxf(a1.x, a1.y));
    g_v [idx] = vx;
    g_vh[idx] = __float2half_rn(vx);
    float2 b0 = *(const float2*)(c2 + base);
    float2 b1 = *(const float2*)(c2 + base + WW);
    g_c2p[idx] = fmaxf(fmaxf(b0.x, b0.y), fmaxf(b1.x, b1.y));
}

// ---------------------------------------------------------------------------
// P1: transpose+split x -> g_xh/g_xl [b][n][c], beta_n = wb . x_n
// ---------------------------------------------------------------------------
__global__ void __launch_bounds__(256) xsplit_kernel(const float* __restrict__ x)
{
    __shared__ float sX [64*65];
    __shared__ float swb[64];
    const int b   = blockIdx.y;
    const int n0  = blockIdx.x * 64;
    const int tid = threadIdx.x;

    if (tid < 64) swb[tid] = g_wb[tid];
    for (int i = tid; i < 4096; i += 256) {
        int c = i >> 6, p = i & 63;
        sX[p*65 + c] = x[(b*CC + c)*NN + n0 + p];
    }
    __syncthreads();

    if (tid < 64) {
        const float* xr = sX + tid*65;
        float acc = 0.f;
        #pragma unroll 8
        for (int c = 0; c < 64; c++) acc += swb[c]*xr[c];
        g_beta[b*NN + n0 + tid] = acc;
    }
    for (int i = tid; i < 2048; i += 256) {
        int p = i >> 5, c0 = (i & 31)*2;
        float f0 = sX[p*65 + c0], f1 = sX[p*65 + c0 + 1];
        __half h0 = __float2half_rn(f0), h1 = __float2half_rn(f1);
        __half l0 = __float2half_rn(f0 - __half2float(h0));
        __half l1 = __float2half_rn(f1 - __half2float(h1));
        size_t base = (size_t)(b*NN + n0 + p)*KK + c0;
        *(__half2*)(g_xh + base) = __halves2half2(h0, h1);
        *(__half2*)(g_xl + base) = __halves2half2(l0, l1);
    }
}

// ---------------------------------------------------------------------------
// P2: kvea, float4-vectorized: ea gate, u' = ea*(G xp), cm = ea*(alpha+bb)
// Thread microtile: 4 pixels x 4 outputs. Weight reads are float4 +
// warp-broadcast; x reads are warp-broadcast scalars.
// ---------------------------------------------------------------------------
__global__ void __launch_bounds__(256) kvea_kernel(
    const float* __restrict__ w_ea1, const float* __restrict__ bn_w,
    const float* __restrict__ bn_b,  const float* __restrict__ bn_m,
    const float* __restrict__ bn_v,  const float* __restrict__ w_ea2,
    const float* __restrict__ b_ea2)
{
    extern __shared__ float sm[];
    float* sG   = sm;                 // [64 c][64 o]  (symmetric, stride 64)
    float* sW1t = sG   + 64*64;       // [128 c][64 o] stride 68 (transposed)
    float* sXp  = sW1t + 128*68;      // [64 p][65]
    float* sC2p = sXp  + 64*65;       // [64 p][65]
    float* sH   = sC2p + 64*65;       // [64 p][65]
    float* sEA  = sH   + 64*65;       // [64]
    float* swb  = sEA  + 64;          // [64]

    const int b   = blockIdx.y;
    const int m0  = blockIdx.x * 64;
    const int tid = threadIdx.x;

    for (int i = tid; i < 64*64; i += 256) sG[i] = g_G[i];   // [c][o] row-major
    // W1 transposed into [c][o], stride 68 (one-time 4-way write conflicts ok)
    for (int i = tid; i < 64*128; i += 256) {
        int o = i >> 7, c = i & 127;
        sW1t[c*68 + o] = w_ea1[i];
    }
    if (tid < 64) swb[tid] = g_wb[tid];
    for (int i = tid; i < 4096; i += 256) {
        int c = i >> 6, p = i & 63;
        sXp [p*65 + c] = g_v  [(b*CC + c)*MM + m0 + p];
        sC2p[p*65 + c] = g_c2p[(b*CC + c)*MM + m0 + p];
    }
    __syncthreads();

    const int ogi = (tid & 15) * 4;   // output group (float4-aligned)
    const int pg  = (tid >> 4) * 4;   // pixel group

    // ---- h = ReLU(BN(W1 [c2p; xp])), 4x4 microtile ------------------------
    {
        float acc[4][4];
        #pragma unroll
        for (int i = 0; i < 4; i++)
            #pragma unroll
            for (int j = 0; j < 4; j++) acc[i][j] = 0.f;

        #pragma unroll 4
        for (int c = 0; c < 64; c++) {
            float4 w = *(const float4*)(sW1t + c*68 + ogi);
            #pragma unroll
            for (int pi = 0; pi < 4; pi++) {
                float cv = sC2p[(pg+pi)*65 + c];
                acc[pi][0] += cv*w.x; acc[pi][1] += cv*w.y;
                acc[pi][2] += cv*w.z; acc[pi][3] += cv*w.w;
            }
        }
        #pragma unroll 4
        for (int c = 0; c < 64; c++) {
            float4 w = *(const float4*)(sW1t + (64+c)*68 + ogi);
            #pragma unroll
            for (int pi = 0; pi < 4; pi++) {
                float xv = sXp[(pg+pi)*65 + c];
                acc[pi][0] += xv*w.x; acc[pi][1] += xv*w.y;
                acc[pi][2] += xv*w.z; acc[pi][3] += xv*w.w;
            }
        }
        #pragma unroll
        for (int oi = 0; oi < 4; oi++) {
            int o = ogi + oi;
            float scale = bn_w[o] * rsqrtf(bn_v[o] + 1e-5f);
            float mo = bn_m[o], bo = bn_b[o];
            #pragma unroll
            for (int pi = 0; pi < 4; pi++) {
                float hv = (acc[pi][oi] - mo) * scale + bo;
                sH[(pg+pi)*65 + o] = fmaxf(hv, 0.f);
            }
        }
    }
    __syncthreads();

    // ---- ea, cm per pixel -------------------------------------------------
    if (tid < 64) {
        int p = tid;
        const float* hr = sH + p*65;
        const float* xr = sXp + p*65;
        float acc = b_ea2[0], alpha = 0.f;
        #pragma unroll 8
        for (int o = 0; o < 64; o++) { acc += w_ea2[o]*hr[o]; alpha += swb[o]*xr[o]; }
        float ea = 1.f / (1.f + __expf(-acc));
        sEA[p] = ea;
        g_eam[b*MM + m0 + p] = ea;
        g_cm [b*MM + m0 + p] = ea * (alpha + g_bb[0]);
    }
    __syncthreads();

    // ---- u' = ea*(G xp), 4x4 microtile, split fp16 ------------------------
    {
        float acc[4][4];
        #pragma unroll
        for (int i = 0; i < 4; i++)
            #pragma unroll
            for (int j = 0; j < 4; j++) acc[i][j] = 0.f;

        #pragma unroll 4
        for (int c = 0; c < 64; c++) {
            float4 w = *(const float4*)(sG + c*64 + ogi);   // G[c][og..og+3]
            #pragma unroll
            for (int pi = 0; pi < 4; pi++) {
                float xv = sXp[(pg+pi)*65 + c];
                acc[pi][0] += xv*w.x; acc[pi][1] += xv*w.y;
                acc[pi][2] += xv*w.z; acc[pi][3] += xv*w.w;
            }
        }
        #pragma unroll
        for (int pi = 0; pi < 4; pi++) {
            float ea = sEA[pg + pi];
            float a0 = acc[pi][0]*ea, a1 = acc[pi][1]*ea;
            float a2 = acc[pi][2]*ea, a3 = acc[pi][3]*ea;
            __half h0 = __float2half_rn(a0), h1 = __float2half_rn(a1);
            __half h2 = __float2half_rn(a2), h3 = __float2half_rn(a3);
            __half l0 = __float2half_rn(a0 - __half2float(h0));
            __half l1 = __float2half_rn(a1 - __half2float(h1));
            __half l2 = __float2half_rn(a2 - __half2float(h2));
            __half l3 = __float2half_rn(a3 - __half2float(h3));
            size_t base = (size_t)(b*MM + m0 + pg + pi)*KK + ogi;
            __half2 hh0 = __halves2half2(h0, h1), hh1 = __halves2half2(h2, h3);
            __half2 ll0 = __halves2half2(l0, l1), ll1 = __halves2half2(l2, l3);
            *(uint2*)(g_uh + base) = make_uint2(*(uint32_t*)&hh0, *(uint32_t*)&hh1);
            *(uint2*)(g_ul + base) = make_uint2(*(uint32_t*)&ll0, *(uint32_t*)&ll1);
        }
    }
}

// ---------------------------------------------------------------------------
// A: flash attention on x vs u', cp.async double-buffered tiles.
// logit = x.u' + cm_col + beta_row*ea_col; P in registers (FA2 style).
// ---------------------------------------------------------------------------
__global__ void __launch_bounds__(256, 2) attn_kernel(
    const float* __restrict__ x, const float* __restrict__ gamma,
    float* __restrict__ out)
{
    extern __shared__ float sm[];
    const uint32_t sb = smem_u32(sm);
    char* smc = (char*)sm;

    const int b    = blockIdx.y;
    const int n0   = blockIdx.x * 128;
    const int tid  = threadIdx.x;
    const int lane = tid & 31;
    const int warp = tid >> 5;
    const int rbase = warp * 16;

    const int lrow  = lane & 15;
    const int khalf = lane >> 4;
    const int gid   = lane >> 2;
    const int colb  = 2 * (lane & 3);
    const int prow0 = rbase + gid;
    const int arow  = rbase + lrow;

    const float g = gamma[0];

    // ---- load X block (pre-split) + beta ----------------------------------
    for (int i = tid; i < 1024; i += 256) {
        int r = i >> 3, u = i & 7;
        size_t gbase = (size_t)(b*NN + n0 + r)*KK + u*8;
        int soff = r*128 + ((u ^ (r&7))<<4);
        *(uint4*)(smc + B_XHI + soff) = *(const uint4*)(g_xh + gbase);
        *(uint4*)(smc + B_XLO + soff) = *(const uint4*)(g_xl + gbase);
    }
    if (tid < 32) *(uint4*)(smc + B_BETA + tid*16) =
        *(const uint4*)(g_beta + b*NN + n0 + tid*4);
    __syncthreads();
    const float beta0 = *(float*)(smc + B_BETA + prow0*4);
    const float beta1 = *(float*)(smc + B_BETA + (prow0+8)*4);

    // ---- prologue: async-load tile 0 into stage 0 -------------------------
    {
        const int mb = 0, s = 0;
        for (int i = tid; i < 512; i += 256) {
            int j = i >> 3, u = i & 7;
            int koff = j*128 + ((u ^ (j&7))<<4);
            size_t kb = (size_t)(b*MM + mb + j)*KK + u*8;
            cpa16(sb + B_ST(s) + ST_UH + koff, g_uh + kb);
            cpa16(sb + B_ST(s) + ST_UL + koff, g_ul + kb);
            size_t vb = (size_t)(b*CC + j)*MM + mb + u*8;
            cpa16(sb + B_ST(s) + ST_VS + koff, g_vh + vb);
        }
        if (tid < 16)      cpa16(sb + B_ST(s) + ST_CM  + tid*16,      g_cm  + b*MM + mb + tid*4);
        else if (tid < 32) cpa16(sb + B_ST(s) + ST_EAM + (tid-16)*16, g_eam + b*MM + mb + (tid-16)*4);
        CPA_COMMIT();
    }

    float m0 = -1e30f, m1 = -1e30f, l0 = 0.f, l1 = 0.f;
    float O[8][4];
    #pragma unroll
    for (int nc = 0; nc < 8; nc++)
        #pragma unroll
        for (int j = 0; j < 4; j++) O[nc][j] = 0.f;

    for (int t = 0; t < MM/64; t++) {
        const int cur = t & 1;
        CPA_WAIT0();
        __syncthreads();   // tile t landed AND all warps done with stage cur

        if (t + 1 < MM/64) {
            const int mb2 = (t+1) * 64, s = cur ^ 1;
            for (int i = tid; i < 512; i += 256) {
                int j = i >> 3, u = i & 7;
                int koff = j*128 + ((u ^ (j&7))<<4);
                size_t kb = (size_t)(b*MM + mb2 + j)*KK + u*8;
                cpa16(sb + B_ST(s) + ST_UH + koff, g_uh + kb);
                cpa16(sb + B_ST(s) + ST_UL + koff, g_ul + kb);
                size_t vb = (size_t)(b*CC + j)*MM + mb2 + u*8;
                cpa16(sb + B_ST(s) + ST_VS + koff, g_vh + vb);
            }
            if (tid < 16)      cpa16(sb + B_ST(s) + ST_CM  + tid*16,      g_cm  + b*MM + mb2 + tid*4);
            else if (tid < 32) cpa16(sb + B_ST(s) + ST_EAM + (tid-16)*16, g_eam + b*MM + mb2 + (tid-16)*4);
            CPA_COMMIT();
        }

        const uint32_t sbK = sb + B_ST(cur);
        char* stc = smc + B_ST(cur);

        // ---- S = X U'^T (3-term fp16 split) -------------------------------
        float S[8][4];
        #pragma unroll
        for (int nc = 0; nc < 8; nc++)
            #pragma unroll
            for (int j = 0; j < 4; j++) S[nc][j] = 0.f;

        #pragma unroll
        for (int kc = 0; kc < 4; kc++) {
            const int unit = kc*2 + khalf;
            uint32_t ah[4], al[4];
            uint32_t aoff = arow*128 + (((unit ^ (arow&7)))<<4);
            ldm4(ah, sb + B_XHI + aoff);
            ldm4(al, sb + B_XLO + aoff);
            #pragma unroll
            for (int nc2 = 0; nc2 < 4; nc2++) {
                int key = nc2*16 + lrow;
                uint32_t boff = key*128 + (((unit ^ (key&7)))<<4);
                uint32_t bh[4];
                ldm4(bh, sbK + ST_UH + boff);
                mma16(S[nc2*2],   ah, bh[0], bh[2]);
                mma16(S[nc2*2+1], ah, bh[1], bh[3]);
                mma16(S[nc2*2],   al, bh[0], bh[2]);
                mma16(S[nc2*2+1], al, bh[1], bh[3]);
                uint32_t bl[4];
                ldm4(bl, sbK + ST_UL + boff);
                mma16(S[nc2*2],   ah, bl[0], bl[2]);
                mma16(S[nc2*2+1], ah, bl[1], bl[3]);
            }
        }

        // ---- bias terms: + cm_col + beta_row*ea_col -----------------------
        #pragma unroll
        for (int nc = 0; nc < 8; nc++) {
            float2 cm2 = *(float2*)(stc + ST_CM  + (nc*8 + colb)*4);
            float2 em2 = *(float2*)(stc + ST_EAM + (nc*8 + colb)*4);
            S[nc][0] += cm2.x + beta0*em2.x;
            S[nc][1] += cm2.y + beta0*em2.y;
            S[nc][2] += cm2.x + beta1*em2.x;
            S[nc][3] += cm2.y + beta1*em2.y;
        }

        // ---- online softmax ----------------------------------------------
        float rm0 = -1e30f, rm1 = -1e30f;
        #pragma unroll
        for (int nc = 0; nc < 8; nc++) {
            rm0 = fmaxf(rm0, fmaxf(S[nc][0], S[nc][1]));
            rm1 = fmaxf(rm1, fmaxf(S[nc][2], S[nc][3]));
        }
        rm0 = fmaxf(rm0, __shfl_xor_sync(0xffffffffu, rm0, 1));
        rm0 = fmaxf(rm0, __shfl_xor_sync(0xffffffffu, rm0, 2));
        rm1 = fmaxf(rm1, __shfl_xor_sync(0xffffffffu, rm1, 1));
        rm1 = fmaxf(rm1, __shfl_xor_sync(0xffffffffu, rm1, 2));
        float mn0 = fmaxf(m0, rm0), mn1 = fmaxf(m1, rm1);
        float a0 = __expf(m0 - mn0), a1 = __expf(m1 - mn1);
        m0 = mn0; m1 = mn1;
        float s0 = 0.f, s1 = 0.f;
        #pragma unroll
        for (int nc = 0; nc < 8; nc++) {
            S[nc][0] = __expf(S[nc][0] - mn0); s0 += S[nc][0];
            S[nc][1] = __expf(S[nc][1] - mn0); s0 += S[nc][1];
            S[nc][2] = __expf(S[nc][2] - mn1); s1 += S[nc][2];
            S[nc][3] = __expf(S[nc][3] - mn1); s1 += S[nc][3];
        }
        s0 += __shfl_xor_sync(0xffffffffu, s0, 1);
        s0 += __shfl_xor_sync(0xffffffffu, s0, 2);
        s1 += __shfl_xor_sync(0xffffffffu, s1, 1);
        s1 += __shfl_xor_sync(0xffffffffu, s1, 2);
        l0 = l0*a0 + s0;
        l1 = l1*a1 + s1;
        #pragma unroll
        for (int nc = 0; nc < 8; nc++) {
            O[nc][0] *= a0; O[nc][1] *= a0;
            O[nc][2] *= a1; O[nc][3] *= a1;
        }

        // ---- pack P into A-fragments (registers) --------------------------
        uint32_t pk[16];
        #pragma unroll
        for (int nc = 0; nc < 8; nc++) {
            pk[nc*2    ] = pack_h2(S[nc][0], S[nc][1]);
            pk[nc*2 + 1] = pack_h2(S[nc][2], S[nc][3]);
        }

        // ---- O += P V^T ---------------------------------------------------
        #pragma unroll
        for (int kc2 = 0; kc2 < 4; kc2++) {
            const int unit = kc2*2 + khalf;
            const uint32_t* a = pk + kc2*4;
            #pragma unroll
            for (int nc2 = 0; nc2 < 4; nc2++) {
                int ch = nc2*16 + lrow;
                uint32_t boff = ch*128 + (((unit ^ (ch&7)))<<4);
                uint32_t bv[4];
                ldm4(bv, sbK + ST_VS + boff);
                mma16(O[nc2*2],   a, bv[0], bv[2]);
                mma16(O[nc2*2+1], a, bv[1], bv[3]);
            }
        }
    }

    // ---- finalize ---------------------------------------------------------
    float inv0 = 1.f / l0, inv1 = 1.f / l1;
    #pragma unroll
    for (int nc = 0; nc < 8; nc++) {
        O[nc][0] *= inv0; O[nc][1] *= inv0;
        O[nc][2] *= inv1; O[nc][3] *= inv1;
    }

    __syncthreads();
    float* Ost = sm;   // [64 ch][128 row] fp32 (32 KB), aliases X regions
    #pragma unroll
    for (int nc = 0; nc < 8; nc++) {
        int c0 = nc*8 + colb;
        Ost[(c0    )*128 + prow0    ] = O[nc][0];
        Ost[(c0 + 1)*128 + prow0    ] = O[nc][1];
        Ost[(c0    )*128 + prow0 + 8] = O[nc][2];
        Ost[(c0 + 1)*128 + prow0 + 8] = O[nc][3];
    }
    __syncthreads();
    for (int i = tid; i < 8192; i += 256) {
        int c = i >> 7, r = i & 127;
        int gi = (b*CC + c)*NN + n0 + r;
        out[gi] = g * Ost[c*128 + r] + x[gi];
    }
}

// ---------------------------------------------------------------------------
extern "C" void kernel_launch(void* const* d_in, const int* in_sizes, int n_in,
                              void* d_out, int out_size)
{
    const float* c2    = (const float*)d_in[0];
    const float* x     = (const float*)d_in[1];
    const float* w_ea1 = (const float*)d_in[2];
    const float* bn_w  = (const float*)d_in[3];
    const float* bn_b  = (const float*)d_in[4];
    const float* bn_m  = (const float*)d_in[5];
    const float* bn_v  = (const float*)d_in[6];
    const float* w_ea2 = (const float*)d_in[7];
    const float* b_ea2 = (const float*)d_in[8];
    const float* w_q   = (const float*)d_in[9];
    const float* b_q   = (const float*)d_in[10];
    const float* gamma = (const float*)d_in[11];
    float* out = (float*)d_out;

    // sG 64*64 + sW1t 128*68 + sXp/sC2p/sH 3*64*65 + 128
    const int KVEA_SMEM = (64*64 + 128*68 + 3*64*65 + 128) * (int)sizeof(float);  // 101888 B

    cudaFuncSetAttribute(kvea_kernel, cudaFuncAttributeMaxDynamicSharedMemorySize, KVEA_SMEM);
    cudaFuncSetAttribute(attn_kernel, cudaFuncAttributeMaxDynamicSharedMemorySize, ATTN_SMEM_BYTES);

    gmat_kernel<<<1, 256>>>(w_q, b_q);
    pool_kernel<<<(BB*CC*MM + 255)/256, 256>>>(x, c2);
    xsplit_kernel<<<dim3(NN/64, BB), 256>>>(x);
    kvea_kernel<<<dim3(MM/64, BB), 256, KVEA_SMEM>>>(w_ea1, bn_w, bn_b, bn_m,
                                                     bn_v, w_ea2, b_ea2);
    attn_kernel<<<dim3(NN/128, BB), 256, ATTN_SMEM_BYTES>>>(x, gamma, out);
}